// round 1
// baseline (speedup 1.0000x reference)
#include <cuda_runtime.h>
#include <math.h>

#define NTOK 16384
#define DIM  4096
#define NE   64
#define BT   128            // tokens per CTA
#define KC   16             // k per chunk
#define NC   (DIM / KC)     // 256 chunks
#define XSTR (BT + 4)       // 132 floats: stride mult of 4 (float4 align), 2-way STS conflict only
#define WSTR (NE + 4)       // 68 floats

typedef unsigned long long u64;

union F4U { float4 f; u64 u[2]; };

__device__ __forceinline__ u64 splat2(float x) {
    u64 r; unsigned u = __float_as_uint(x);
    asm("mov.b64 %0, {%1, %2};" : "=l"(r) : "r"(u), "r"(u));
    return r;
}
__device__ __forceinline__ void ffma2(u64& d, u64 a, u64 b) {
    asm("fma.rn.f32x2 %0, %1, %2, %0;" : "+l"(d) : "l"(a), "l"(b));
}
__device__ __forceinline__ bool better(float v, int i, float V, int I) {
    return (v > V) || (v == V && i < I);
}

__global__ __launch_bounds__(256, 1)
void gating_kernel(const float* __restrict__ X, const float* __restrict__ W,
                   const float* __restrict__ B, float* __restrict__ out, int voff)
{
    __shared__ float xs[2][KC * XSTR];
    __shared__ float ws[2][KC * WSTR];

    const int tid    = threadIdx.x;
    const int token0 = blockIdx.x * BT;
    const int ec     = tid & 7;    // expert column: experts [ec*8, ec*8+8)
    const int tr     = tid >> 3;   // token row: tokens [tr*4, tr*4+4)

    u64 acc[4][4];
    #pragma unroll
    for (int t = 0; t < 4; t++)
        #pragma unroll
        for (int p = 0; p < 4; p++) acc[t][p] = 0ull;

    float4 xr[2]; float4 wr;

    auto load_chunk = [&](int c) {
        const float* xp = X + (long)token0 * DIM + c * KC;
        #pragma unroll
        for (int i = 0; i < 2; i++) {
            int f = tid + 256 * i; int t = f >> 2, kg = f & 3;
            xr[i] = *(const float4*)(xp + (long)t * DIM + kg * 4);
        }
        { int e = tid >> 2, kg = tid & 3;
          wr = *(const float4*)(W + (long)e * DIM + c * KC + kg * 4); }
    };
    auto store_chunk = [&](int b) {
        #pragma unroll
        for (int i = 0; i < 2; i++) {
            int f = tid + 256 * i; int t = f >> 2, kg = f & 3;
            xs[b][(kg * 4 + 0) * XSTR + t] = xr[i].x;
            xs[b][(kg * 4 + 1) * XSTR + t] = xr[i].y;
            xs[b][(kg * 4 + 2) * XSTR + t] = xr[i].z;
            xs[b][(kg * 4 + 3) * XSTR + t] = xr[i].w;
        }
        { int e = tid >> 2, kg = tid & 3;
          ws[b][(kg * 4 + 0) * WSTR + e] = wr.x;
          ws[b][(kg * 4 + 1) * WSTR + e] = wr.y;
          ws[b][(kg * 4 + 2) * WSTR + e] = wr.z;
          ws[b][(kg * 4 + 3) * WSTR + e] = wr.w; }
    };

    load_chunk(0);
    store_chunk(0);

    for (int c = 0; c < NC; c++) {
        __syncthreads();
        const int cb = c & 1;
        if (c + 1 < NC) load_chunk(c + 1);

        #pragma unroll
        for (int k = 0; k < KC; k++) {
            const float4 xv = *(const float4*)&xs[cb][k * XSTR + tr * 4];
            F4U wa, wb;
            wa.f = *(const float4*)&ws[cb][k * WSTR + ec * 8];
            wb.f = *(const float4*)&ws[cb][k * WSTR + ec * 8 + 4];
            const u64 s0 = splat2(xv.x), s1 = splat2(xv.y),
                      s2 = splat2(xv.z), s3 = splat2(xv.w);
            ffma2(acc[0][0], s0, wa.u[0]); ffma2(acc[0][1], s0, wa.u[1]);
            ffma2(acc[0][2], s0, wb.u[0]); ffma2(acc[0][3], s0, wb.u[1]);
            ffma2(acc[1][0], s1, wa.u[0]); ffma2(acc[1][1], s1, wa.u[1]);
            ffma2(acc[1][2], s1, wb.u[0]); ffma2(acc[1][3], s1, wb.u[1]);
            ffma2(acc[2][0], s2, wa.u[0]); ffma2(acc[2][1], s2, wa.u[1]);
            ffma2(acc[2][2], s2, wb.u[0]); ffma2(acc[2][3], s2, wb.u[1]);
            ffma2(acc[3][0], s3, wa.u[0]); ffma2(acc[3][1], s3, wa.u[1]);
            ffma2(acc[3][2], s3, wb.u[0]); ffma2(acc[3][3], s3, wb.u[1]);
        }

        if (c + 1 < NC) store_chunk((c + 1) & 1);
    }

    // ---- Epilogue: bias + softmax + top-2, via 8-lane shuffle groups ----
    float bb[8];
    #pragma unroll
    for (int e = 0; e < 8; e++) bb[e] = B[ec * 8 + e];

    #pragma unroll
    for (int t = 0; t < 4; t++) {
        float sc[8];
        #pragma unroll
        for (int p = 0; p < 4; p++) {
            sc[2 * p]     = __uint_as_float((unsigned)(acc[t][p] & 0xffffffffu)) + bb[2 * p];
            sc[2 * p + 1] = __uint_as_float((unsigned)(acc[t][p] >> 32))         + bb[2 * p + 1];
        }

        // group max over 64 experts
        float m = sc[0];
        #pragma unroll
        for (int e = 1; e < 8; e++) m = fmaxf(m, sc[e]);
        #pragma unroll
        for (int d = 1; d < 8; d <<= 1) m = fmaxf(m, __shfl_xor_sync(0xffffffffu, m, d));

        // sum of exp
        float se = 0.f;
        #pragma unroll
        for (int e = 0; e < 8; e++) se += expf(sc[e] - m);
        #pragma unroll
        for (int d = 1; d < 8; d <<= 1) se += __shfl_xor_sync(0xffffffffu, se, d);

        // local top-2 (first occurrence wins ties -> lower index)
        float v1 = -1e30f, v2 = -1e30f; int i1 = -1, i2 = -1;
        #pragma unroll
        for (int e = 0; e < 8; e++) {
            const float s = sc[e]; const int eg = ec * 8 + e;
            if (s > v1) { v2 = v1; i2 = i1; v1 = s; i1 = eg; }
            else if (s > v2) { v2 = s; i2 = eg; }
        }
        // merge across 8 lanes
        #pragma unroll
        for (int d = 1; d < 8; d <<= 1) {
            const float ov1 = __shfl_xor_sync(0xffffffffu, v1, d);
            const float ov2 = __shfl_xor_sync(0xffffffffu, v2, d);
            const int   oi1 = __shfl_xor_sync(0xffffffffu, i1, d);
            const int   oi2 = __shfl_xor_sync(0xffffffffu, i2, d);
            if (better(ov1, oi1, v1, i1)) {
                float nv2; int ni2;
                if (better(v1, i1, ov2, oi2)) { nv2 = v1; ni2 = i1; }
                else                          { nv2 = ov2; ni2 = oi2; }
                v1 = ov1; i1 = oi1; v2 = nv2; i2 = ni2;
            } else if (better(ov1, oi1, v2, i2)) {
                v2 = ov1; i2 = oi1;
            }
        }

        if (ec == 0) {
            const int g = token0 + tr * 4 + t;
            const float inv = 1.0f / se;
            out[g * 2 + 0]        = (float)i1;
            out[g * 2 + 1]        = (float)i2;
            out[voff + g * 2 + 0] = expf(v1 - m) * inv;
            out[voff + g * 2 + 1] = expf(v2 - m) * inv;
        }
    }
}

extern "C" void kernel_launch(void* const* d_in, const int* in_sizes, int n_in,
                              void* d_out, int out_size) {
    const float* x = (const float*)d_in[0];
    const float* W = (const float*)d_in[1];
    const float* b = (const float*)d_in[2];
    float* out = (float*)d_out;
    gating_kernel<<<NTOK / BT, 256>>>(x, W, b, out, out_size / 2);
}

// round 4
// speedup vs baseline: 1.5817x; 1.5817x over previous
#include <cuda_runtime.h>
#include <cstdint>
#include <math.h>

#define NTOK 16384
#define DIM  4096
#define NE   64
#define BT   128                  // tokens per CTA (M), 8 warps x m16
#define KT   32                   // K per chunk (4 k-steps of 8)
#define NCH  (DIM / KT)           // 128
#define NBUF 4
#define ASTR 36                   // padded float stride (bank-shift 4/row)
#define WSTR 36
#define ABYTES (BT * ASTR * 4)    // 18432
#define WBYTES (NE * WSTR * 4)    // 9216
#define BUFB   (ABYTES + WBYTES)  // 27648
#define SMEM_DYN (NBUF * BUFB)    // 110592
#define SCSTR 66                  // epilogue score stride (even -> float2 aligned)

static __device__ __forceinline__ uint32_t smem_u32(const void* p) {
    uint32_t a;
    asm("{ .reg .u64 t; cvta.to.shared.u64 t, %1; cvt.u32.u64 %0, t; }"
        : "=r"(a) : "l"(p));
    return a;
}
static __device__ __forceinline__ void cp16(uint32_t dst, const void* src) {
    asm volatile("cp.async.cg.shared.global [%0], [%1], 16;"
                 :: "r"(dst), "l"(src) : "memory");
}
#define CP_COMMIT() asm volatile("cp.async.commit_group;" ::: "memory")
#define CP_WAIT(n)  asm volatile("cp.async.wait_group %0;" :: "n"(n) : "memory")

// split fp32 -> tf32 hi + tf32 lo (x ~= hi + lo, residual ~2^-22 |x|)
static __device__ __forceinline__ void split_tf32(float v, uint32_t& hi, uint32_t& lo) {
    asm("cvt.rna.tf32.f32 %0, %1;" : "=r"(hi) : "f"(v));
    const float l = v - __uint_as_float(hi);
    asm("cvt.rna.tf32.f32 %0, %1;" : "=r"(lo) : "f"(l));
}
static __device__ __forceinline__ void mma8(float* c, const uint32_t* a, const uint32_t* b) {
    asm volatile(
        "mma.sync.aligned.m16n8k8.row.col.f32.tf32.tf32.f32 "
        "{%0,%1,%2,%3}, {%4,%5,%6,%7}, {%8,%9}, {%0,%1,%2,%3};"
        : "+f"(c[0]), "+f"(c[1]), "+f"(c[2]), "+f"(c[3])
        : "r"(a[0]), "r"(a[1]), "r"(a[2]), "r"(a[3]), "r"(b[0]), "r"(b[1]));
}

__global__ __launch_bounds__(256, 1)
void gating_mma(const float* __restrict__ X, const float* __restrict__ W,
                const float* __restrict__ B, float* __restrict__ out, int voff)
{
    extern __shared__ char smem[];
    const int tid  = threadIdx.x;
    const int wid  = tid >> 5;
    const int lane = tid & 31;
    const int qid  = lane >> 2;        // group id (fragment row)
    const int qt   = lane & 3;         // thread-in-group (fragment col)
    const int token0 = blockIdx.x * BT;

    const uint32_t sbase = smem_u32(smem);

    // ---- producer mapping (256 threads) ----
    const int arow = tid >> 1, aseg0 = (tid & 1) * 4;   // A: 128 rows x 8 segs(16B), 4/thread
    const int wrow = tid >> 2, wseg0 = (tid & 3) * 2;   // W: 64 rows x 8 segs, 2/thread
    const float* agp = X + (size_t)(token0 + arow) * DIM;
    const float* wgp = W + (size_t)wrow * DIM;

    auto issue_chunk = [&](int c) {
        const uint32_t ab = sbase + (uint32_t)(c % NBUF) * BUFB;
        const uint32_t wb = ab + ABYTES;
        const float* ag = agp + c * KT;
        #pragma unroll
        for (int j = 0; j < 4; j++)
            cp16(ab + (uint32_t)arow * (ASTR * 4) + (aseg0 + j) * 16, ag + (aseg0 + j) * 4);
        const float* wg = wgp + c * KT;
        #pragma unroll
        for (int j = 0; j < 2; j++)
            cp16(wb + (uint32_t)wrow * (WSTR * 4) + (wseg0 + j) * 16, wg + (wseg0 + j) * 4);
    };

    float acc[8][4];
    #pragma unroll
    for (int nt = 0; nt < 8; nt++)
        #pragma unroll
        for (int j = 0; j < 4; j++) acc[nt][j] = 0.f;

    issue_chunk(0); CP_COMMIT();
    issue_chunk(1); CP_COMMIT();
    issue_chunk(2); CP_COMMIT();

    #pragma unroll 1
    for (int c = 0; c < NCH; c++) {
        CP_WAIT(2);
        __syncthreads();

        const float* As = (const float*)(smem + (c % NBUF) * BUFB);
        const float* Ws = (const float*)(smem + (c % NBUF) * BUFB + ABYTES);
        const int ar0 = (wid * 16 + qid) * ASTR;

        #pragma unroll
        for (int kk = 0; kk < 4; kk++) {
            const int kc = kk * 8 + qt;
            // A fragment (m16k8), rows wid*16 + {qid, qid+8}, cols {qt, qt+4}
            uint32_t ah[4], al[4];
            split_tf32(As[ar0 + kc],                 ah[0], al[0]);
            split_tf32(As[ar0 + 8 * ASTR + kc],      ah[1], al[1]);
            split_tf32(As[ar0 + kc + 4],             ah[2], al[2]);
            split_tf32(As[ar0 + 8 * ASTR + kc + 4],  ah[3], al[3]);

            // B fragments for 8 n-tiles (n8k8, col-major == W[n][k])
            uint32_t bh[16], bl[16];
            #pragma unroll
            for (int nt = 0; nt < 8; nt++) {
                const int br = (nt * 8 + qid) * WSTR + kc;
                split_tf32(Ws[br],     bh[2 * nt],     bl[2 * nt]);
                split_tf32(Ws[br + 4], bh[2 * nt + 1], bl[2 * nt + 1]);
            }

            #pragma unroll
            for (int nt = 0; nt < 8; nt++) mma8(acc[nt], ah, bh + 2 * nt);
            #pragma unroll
            for (int nt = 0; nt < 8; nt++) mma8(acc[nt], ah, bl + 2 * nt);
            #pragma unroll
            for (int nt = 0; nt < 8; nt++) mma8(acc[nt], al, bh + 2 * nt);
        }

        if (c + 3 < NCH) issue_chunk(c + 3);
        CP_COMMIT();   // uniform group accounting (empty group near the tail)
    }

    CP_WAIT(0);
    __syncthreads();

    // ---- scores -> smem (bias fused), then per-token softmax + top-2 ----
    float* SC = (float*)smem;
    {
        const int r0 = wid * 16 + qid, r1 = r0 + 8;
        #pragma unroll
        for (int nt = 0; nt < 8; nt++) {
            const int cb = nt * 8 + qt * 2;
            const float b0 = __ldg(B + cb), b1 = __ldg(B + cb + 1);
            *(float2*)(SC + r0 * SCSTR + cb) = make_float2(acc[nt][0] + b0, acc[nt][1] + b1);
            *(float2*)(SC + r1 * SCSTR + cb) = make_float2(acc[nt][2] + b0, acc[nt][3] + b1);
        }
    }
    __syncthreads();

    if (tid < BT) {
        const float* row = SC + tid * SCSTR;
        float m = row[0];
        #pragma unroll
        for (int e = 1; e < NE; e++) m = fmaxf(m, row[e]);

        float se = 0.f;
        #pragma unroll
        for (int e = 0; e < NE; e++) se += __expf(row[e] - m);

        float v1 = -1e30f, v2 = -1e30f; int i1 = -1, i2 = -1;
        #pragma unroll
        for (int e = 0; e < NE; e++) {
            const float s = row[e];
            if (s > v1)      { v2 = v1; i2 = i1; v1 = s; i1 = e; }
            else if (s > v2) { v2 = s; i2 = e; }
        }

        const int g = token0 + tid;
        const float inv = 1.0f / se;
        out[g * 2 + 0]        = (float)i1;
        out[g * 2 + 1]        = (float)i2;
        out[voff + g * 2 + 0] = __expf(v1 - m) * inv;
        out[voff + g * 2 + 1] = __expf(v2 - m) * inv;
    }
}

extern "C" void kernel_launch(void* const* d_in, const int* in_sizes, int n_in,
                              void* d_out, int out_size) {
    const float* x = (const float*)d_in[0];
    const float* W = (const float*)d_in[1];
    const float* b = (const float*)d_in[2];
    float* out = (float*)d_out;
    cudaFuncSetAttribute(gating_mma, cudaFuncAttributeMaxDynamicSharedMemorySize, SMEM_DYN);
    gating_mma<<<NTOK / BT, 256, SMEM_DYN>>>(x, W, b, out, out_size / 2);
}

// round 5
// speedup vs baseline: 1.7299x; 1.0937x over previous
#include <cuda_runtime.h>
#include <cstdint>
#include <math.h>

#define NTOK 16384
#define DIM  4096
#define NE   64
#define BT   128                  // tokens per CTA (M): 8 m16 stripes
#define KT   32                   // K per chunk (4 k-steps of 8)
#define NCH  (DIM / KT)           // 128
#define NBUF 4
#define NTHR 512
#define ASTR 36                   // A smem stride in floats (bank-clean)
#define WS2  36                   // W smem stride in uint2 (8*(qid%4)+2qt injective)
#define ABYTES (BT * ASTR * 4)    // 18432
#define WBYTES (NE * WS2 * 8)     // 18432
#define BUFB   (ABYTES + WBYTES)  // 36864
#define SMEM_DYN (NBUF * BUFB)    // 147456
#define SCSTR 66

static __device__ __forceinline__ uint32_t smem_u32(const void* p) {
    uint32_t a;
    asm("{ .reg .u64 t; cvta.to.shared.u64 t, %1; cvt.u32.u64 %0, t; }"
        : "=r"(a) : "l"(p));
    return a;
}
static __device__ __forceinline__ void cp16(uint32_t dst, const void* src) {
    asm volatile("cp.async.cg.shared.global [%0], [%1], 16;"
                 :: "r"(dst), "l"(src) : "memory");
}
#define CP_COMMIT() asm volatile("cp.async.commit_group;" ::: "memory")
#define CP_WAIT(n)  asm volatile("cp.async.wait_group %0;" :: "n"(n) : "memory")

static __device__ __forceinline__ void split_tf32(float v, uint32_t& hi, uint32_t& lo) {
    asm("cvt.rna.tf32.f32 %0, %1;" : "=r"(hi) : "f"(v));
    const float l = v - __uint_as_float(hi);
    asm("cvt.rna.tf32.f32 %0, %1;" : "=r"(lo) : "f"(l));
}
static __device__ __forceinline__ void mma8(float* c, const uint32_t* a,
                                            uint32_t b0, uint32_t b1) {
    asm volatile(
        "mma.sync.aligned.m16n8k8.row.col.f32.tf32.tf32.f32 "
        "{%0,%1,%2,%3}, {%4,%5,%6,%7}, {%8,%9}, {%0,%1,%2,%3};"
        : "+f"(c[0]), "+f"(c[1]), "+f"(c[2]), "+f"(c[3])
        : "r"(a[0]), "r"(a[1]), "r"(a[2]), "r"(a[3]), "r"(b0), "r"(b1));
}

// Pre-split weights: W[e][k] -> (tf32 hi, tf32 lo), interleaved.
__device__ uint2 g_wsplit[NE * DIM];

__global__ void split_w_kernel(const float* __restrict__ W) {
    const int i = blockIdx.x * blockDim.x + threadIdx.x;
    if (i < NE * DIM) {
        uint32_t hi, lo;
        split_tf32(W[i], hi, lo);
        g_wsplit[i] = make_uint2(hi, lo);
    }
}

__global__ __launch_bounds__(NTHR, 1)
void gating_mma(const float* __restrict__ X, const float* __restrict__ B,
                float* __restrict__ out, int voff)
{
    extern __shared__ char smem[];
    const int tid    = threadIdx.x;
    const int wid    = tid >> 5;
    const int lane   = tid & 31;
    const int qid    = lane >> 2;
    const int qt     = lane & 3;
    const int stripe = wid & 7;        // m16 stripe 0..7
    const int nhalf  = wid >> 3;       // expert half: 0 -> experts 0..31, 1 -> 32..63
    const int token0 = blockIdx.x * BT;

    const uint32_t sbase = smem_u32(smem);

    // ---- producer mapping (512 threads, 2 cp16 each per tile) ----
    const int arow = tid >> 2, aseg0 = (tid & 3) * 2;   // A: 128 rows x 8 segs(16B)
    const int wrow = tid >> 3, wseg0 = (tid & 7) * 2;   // W: 64 rows x 16 segs(16B)
    const float* agp = X + (size_t)(token0 + arow) * DIM;
    const uint2* wgp = g_wsplit + (size_t)wrow * DIM;

    auto issue_chunk = [&](int c) {
        const uint32_t ab = sbase + (uint32_t)(c & (NBUF - 1)) * BUFB;
        const uint32_t wb = ab + ABYTES;
        const float* ag = agp + c * KT;
        #pragma unroll
        for (int j = 0; j < 2; j++)
            cp16(ab + (uint32_t)arow * (ASTR * 4) + (aseg0 + j) * 16, ag + (aseg0 + j) * 4);
        const uint2* wg = wgp + c * KT;
        #pragma unroll
        for (int j = 0; j < 2; j++)
            cp16(wb + (uint32_t)wrow * (WS2 * 8) + (wseg0 + j) * 16, wg + (wseg0 + j) * 2);
    };

    float acc[4][4];
    #pragma unroll
    for (int nt = 0; nt < 4; nt++)
        #pragma unroll
        for (int j = 0; j < 4; j++) acc[nt][j] = 0.f;

    issue_chunk(0); CP_COMMIT();
    issue_chunk(1); CP_COMMIT();
    issue_chunk(2); CP_COMMIT();

    const int ar0 = (stripe * 16 + qid) * ASTR;
    const int wr0 = nhalf * 32 + qid;

    #pragma unroll 1
    for (int c = 0; c < NCH; c++) {
        CP_WAIT(2);
        __syncthreads();

        const char* buf = smem + (c & (NBUF - 1)) * BUFB;
        const float* As = (const float*)buf;
        const uint2* Ws = (const uint2*)(buf + ABYTES);

        #pragma unroll
        for (int kk = 0; kk < 4; kk++) {
            const int kc = kk * 8 + qt;

            uint32_t ah[4], al[4];
            split_tf32(As[ar0 + kc],                ah[0], al[0]);
            split_tf32(As[ar0 + 8 * ASTR + kc],     ah[1], al[1]);
            split_tf32(As[ar0 + kc + 4],            ah[2], al[2]);
            split_tf32(As[ar0 + 8 * ASTR + kc + 4], ah[3], al[3]);

            uint2 b0[4], b1[4];
            #pragma unroll
            for (int nt = 0; nt < 4; nt++) {
                const int br = (wr0 + nt * 8) * WS2 + kc;
                b0[nt] = Ws[br];
                b1[nt] = Ws[br + 4];
            }

            #pragma unroll
            for (int nt = 0; nt < 4; nt++) mma8(acc[nt], ah, b0[nt].x, b1[nt].x); // Ah*Bh
            #pragma unroll
            for (int nt = 0; nt < 4; nt++) mma8(acc[nt], ah, b0[nt].y, b1[nt].y); // Ah*Bl
            #pragma unroll
            for (int nt = 0; nt < 4; nt++) mma8(acc[nt], al, b0[nt].x, b1[nt].x); // Al*Bh
        }

        if (c + 3 < NCH) issue_chunk(c + 3);
        CP_COMMIT();   // uniform group accounting
    }

    CP_WAIT(0);
    __syncthreads();

    // ---- scores -> smem (bias fused), then per-token softmax + top-2 ----
    float* SC = (float*)smem;
    {
        const int r0 = stripe * 16 + qid, r1 = r0 + 8;
        #pragma unroll
        for (int nt = 0; nt < 4; nt++) {
            const int cb = nhalf * 32 + nt * 8 + qt * 2;
            const float b0 = __ldg(B + cb), b1 = __ldg(B + cb + 1);
            *(float2*)(SC + r0 * SCSTR + cb) = make_float2(acc[nt][0] + b0, acc[nt][1] + b1);
            *(float2*)(SC + r1 * SCSTR + cb) = make_float2(acc[nt][2] + b0, acc[nt][3] + b1);
        }
    }
    __syncthreads();

    if (tid < BT) {
        const float* row = SC + tid * SCSTR;
        float m = row[0];
        #pragma unroll
        for (int e = 1; e < NE; e++) m = fmaxf(m, row[e]);

        float se = 0.f;
        #pragma unroll
        for (int e = 0; e < NE; e++) se += __expf(row[e] - m);

        float v1 = -1e30f, v2 = -1e30f; int i1 = -1, i2 = -1;
        #pragma unroll
        for (int e = 0; e < NE; e++) {
            const float s = row[e];
            if (s > v1)      { v2 = v1; i2 = i1; v1 = s; i1 = e; }
            else if (s > v2) { v2 = s; i2 = e; }
        }

        const int g = token0 + tid;
        const float inv = 1.0f / se;
        out[g * 2 + 0]        = (float)i1;
        out[g * 2 + 1]        = (float)i2;
        out[voff + g * 2 + 0] = __expf(v1 - m) * inv;
        out[voff + g * 2 + 1] = __expf(v2 - m) * inv;
    }
}

extern "C" void kernel_launch(void* const* d_in, const int* in_sizes, int n_in,
                              void* d_out, int out_size) {
    const float* x = (const float*)d_in[0];
    const float* W = (const float*)d_in[1];
    const float* b = (const float*)d_in[2];
    float* out = (float*)d_out;

    split_w_kernel<<<(NE * DIM + 255) / 256, 256>>>(W);

    cudaFuncSetAttribute(gating_mma, cudaFuncAttributeMaxDynamicSharedMemorySize, SMEM_DYN);
    gating_mma<<<NTOK / BT, NTHR, SMEM_DYN>>>(x, b, out, out_size / 2);
}

// round 6
// speedup vs baseline: 1.7305x; 1.0003x over previous
#include <cuda_runtime.h>
#include <cstdint>
#include <math.h>

#define NTOK 16384
#define DIM  4096
#define NE   64
#define BT   128                  // tokens per CTA (M): 8 m16 stripes
#define KT   32                   // K per chunk (4 k-steps of 8)
#define NCH  (DIM / KT)           // 128
#define NBUF 4
#define NTHR 512
#define ASTR 36                   // A smem stride in floats (bank-clean)
#define WS2  36                   // W smem stride in uint2 (8*(qid%4)+2qt injective)
#define ABYTES (BT * ASTR * 4)    // 18432
#define WBYTES (NE * WS2 * 8)     // 18432
#define BUFB   (ABYTES + WBYTES)  // 36864
#define SMEM_DYN (NBUF * BUFB)    // 147456
#define SCSTR 66

static __device__ __forceinline__ uint32_t smem_u32(const void* p) {
    uint32_t a;
    asm("{ .reg .u64 t; cvta.to.shared.u64 t, %1; cvt.u32.u64 %0, t; }"
        : "=r"(a) : "l"(p));
    return a;
}
static __device__ __forceinline__ void cp16(uint32_t dst, const void* src) {
    asm volatile("cp.async.cg.shared.global [%0], [%1], 16;"
                 :: "r"(dst), "l"(src) : "memory");
}
#define CP_COMMIT() asm volatile("cp.async.commit_group;" ::: "memory")
#define CP_WAIT(n)  asm volatile("cp.async.wait_group %0;" :: "n"(n) : "memory")

static __device__ __forceinline__ void split_tf32(float v, uint32_t& hi, uint32_t& lo) {
    asm("cvt.rna.tf32.f32 %0, %1;" : "=r"(hi) : "f"(v));
    const float l = v - __uint_as_float(hi);
    asm("cvt.rna.tf32.f32 %0, %1;" : "=r"(lo) : "f"(l));
}
static __device__ __forceinline__ void mma8(float* c, const uint32_t* a,
                                            uint32_t b0, uint32_t b1) {
    asm volatile(
        "mma.sync.aligned.m16n8k8.row.col.f32.tf32.tf32.f32 "
        "{%0,%1,%2,%3}, {%4,%5,%6,%7}, {%8,%9}, {%0,%1,%2,%3};"
        : "+f"(c[0]), "+f"(c[1]), "+f"(c[2]), "+f"(c[3])
        : "r"(a[0]), "r"(a[1]), "r"(a[2]), "r"(a[3]), "r"(b0), "r"(b1));
}

// Pre-split weights: W[e][k] -> (tf32 hi, tf32 lo), interleaved.
__device__ uint2 g_wsplit[NE * DIM];

__global__ void split_w_kernel(const float* __restrict__ W) {
    const int i = blockIdx.x * blockDim.x + threadIdx.x;
    if (i < NE * DIM) {
        uint32_t hi, lo;
        split_tf32(W[i], hi, lo);
        g_wsplit[i] = make_uint2(hi, lo);
    }
}

__global__ __launch_bounds__(NTHR, 1)
void gating_mma(const float* __restrict__ X, const float* __restrict__ B,
                float* __restrict__ out, int voff)
{
    extern __shared__ char smem[];
    const int tid    = threadIdx.x;
    const int wid    = tid >> 5;
    const int lane   = tid & 31;
    const int qid    = lane >> 2;
    const int qt     = lane & 3;
    const int stripe = wid & 7;        // m16 stripe 0..7
    const int nhalf  = wid >> 3;       // expert half: 0 -> experts 0..31, 1 -> 32..63
    const int token0 = blockIdx.x * BT;

    const uint32_t sbase = smem_u32(smem);

    // ---- producer mapping (512 threads, 2 cp16 each per tile) ----
    const int arow = tid >> 2, aseg0 = (tid & 3) * 2;   // A: 128 rows x 8 segs(16B)
    const int wrow = tid >> 3, wseg0 = (tid & 7) * 2;   // W: 64 rows x 16 segs(16B)
    const float* agp = X + (size_t)(token0 + arow) * DIM;
    const uint2* wgp = g_wsplit + (size_t)wrow * DIM;

    auto issue_chunk = [&](int c) {
        const uint32_t ab = sbase + (uint32_t)(c & (NBUF - 1)) * BUFB;
        const uint32_t wb = ab + ABYTES;
        const float* ag = agp + c * KT;
        #pragma unroll
        for (int j = 0; j < 2; j++)
            cp16(ab + (uint32_t)arow * (ASTR * 4) + (aseg0 + j) * 16, ag + (aseg0 + j) * 4);
        const uint2* wg = wgp + c * KT;
        #pragma unroll
        for (int j = 0; j < 2; j++)
            cp16(wb + (uint32_t)wrow * (WS2 * 8) + (wseg0 + j) * 16, wg + (wseg0 + j) * 2);
    };

    float acc[4][4];
    #pragma unroll
    for (int nt = 0; nt < 4; nt++)
        #pragma unroll
        for (int j = 0; j < 4; j++) acc[nt][j] = 0.f;

    issue_chunk(0); CP_COMMIT();
    issue_chunk(1); CP_COMMIT();
    issue_chunk(2); CP_COMMIT();

    const int ar0 = (stripe * 16 + qid) * ASTR;
    const int wr0 = nhalf * 32 + qid;

    #pragma unroll 1
    for (int c = 0; c < NCH; c++) {
        CP_WAIT(2);
        __syncthreads();

        const char* buf = smem + (c & (NBUF - 1)) * BUFB;
        const float* As = (const float*)buf;
        const uint2* Ws = (const uint2*)(buf + ABYTES);

        #pragma unroll
        for (int kk = 0; kk < 4; kk++) {
            const int kc = kk * 8 + qt;

            uint32_t ah[4], al[4];
            split_tf32(As[ar0 + kc],                ah[0], al[0]);
            split_tf32(As[ar0 + 8 * ASTR + kc],     ah[1], al[1]);
            split_tf32(As[ar0 + kc + 4],            ah[2], al[2]);
            split_tf32(As[ar0 + 8 * ASTR + kc + 4], ah[3], al[3]);

            uint2 b0[4], b1[4];
            #pragma unroll
            for (int nt = 0; nt < 4; nt++) {
                const int br = (wr0 + nt * 8) * WS2 + kc;
                b0[nt] = Ws[br];
                b1[nt] = Ws[br + 4];
            }

            #pragma unroll
            for (int nt = 0; nt < 4; nt++) mma8(acc[nt], ah, b0[nt].x, b1[nt].x); // Ah*Bh
            #pragma unroll
            for (int nt = 0; nt < 4; nt++) mma8(acc[nt], ah, b0[nt].y, b1[nt].y); // Ah*Bl
            #pragma unroll
            for (int nt = 0; nt < 4; nt++) mma8(acc[nt], al, b0[nt].x, b1[nt].x); // Al*Bh
        }

        if (c + 3 < NCH) issue_chunk(c + 3);
        CP_COMMIT();   // uniform group accounting
    }

    CP_WAIT(0);
    __syncthreads();

    // ---- scores -> smem (bias fused), then per-token softmax + top-2 ----
    float* SC = (float*)smem;
    {
        const int r0 = stripe * 16 + qid, r1 = r0 + 8;
        #pragma unroll
        for (int nt = 0; nt < 4; nt++) {
            const int cb = nhalf * 32 + nt * 8 + qt * 2;
            const float b0 = __ldg(B + cb), b1 = __ldg(B + cb + 1);
            *(float2*)(SC + r0 * SCSTR + cb) = make_float2(acc[nt][0] + b0, acc[nt][1] + b1);
            *(float2*)(SC + r1 * SCSTR + cb) = make_float2(acc[nt][2] + b0, acc[nt][3] + b1);
        }
    }
    __syncthreads();

    if (tid < BT) {
        const float* row = SC + tid * SCSTR;
        float m = row[0];
        #pragma unroll
        for (int e = 1; e < NE; e++) m = fmaxf(m, row[e]);

        float se = 0.f;
        #pragma unroll
        for (int e = 0; e < NE; e++) se += __expf(row[e] - m);

        float v1 = -1e30f, v2 = -1e30f; int i1 = -1, i2 = -1;
        #pragma unroll
        for (int e = 0; e < NE; e++) {
            const float s = row[e];
            if (s > v1)      { v2 = v1; i2 = i1; v1 = s; i1 = e; }
            else if (s > v2) { v2 = s; i2 = e; }
        }

        const int g = token0 + tid;
        const float inv = 1.0f / se;
        out[g * 2 + 0]        = (float)i1;
        out[g * 2 + 1]        = (float)i2;
        out[voff + g * 2 + 0] = __expf(v1 - m) * inv;
        out[voff + g * 2 + 1] = __expf(v2 - m) * inv;
    }
}

extern "C" void kernel_launch(void* const* d_in, const int* in_sizes, int n_in,
                              void* d_out, int out_size) {
    const float* x = (const float*)d_in[0];
    const float* W = (const float*)d_in[1];
    const float* b = (const float*)d_in[2];
    float* out = (float*)d_out;

    split_w_kernel<<<(NE * DIM + 255) / 256, 256>>>(W);

    cudaFuncSetAttribute(gating_mma, cudaFuncAttributeMaxDynamicSharedMemorySize, SMEM_DYN);
    gating_mma<<<NTOK / BT, NTHR, SMEM_DYN>>>(x, b, out, out_size / 2);
}

// round 7
// speedup vs baseline: 1.7348x; 1.0025x over previous
#include <cuda_runtime.h>
#include <cstdint>
#include <math.h>

#define NTOK 16384
#define DIM  4096
#define NE   64
#define BT   128                  // tokens per CTA (M): 8 m16 stripes
#define KT   32                   // K per chunk (4 k-steps of 8)
#define NCH  (DIM / KT)           // 128
#define NBUF 4
#define NTHR 512
#define ASTR 36                   // A smem stride in floats (bank-clean)
#define WS2  36                   // W smem stride in uint2 (8*(qid%4)+2qt injective)
#define ABYTES (BT * ASTR * 4)    // 18432
#define WBYTES (NE * WS2 * 8)     // 18432
#define BUFB   (ABYTES + WBYTES)  // 36864
#define SMEM_DYN (NBUF * BUFB)    // 147456
#define SCSTR 66

static __device__ __forceinline__ uint32_t smem_u32(const void* p) {
    uint32_t a;
    asm("{ .reg .u64 t; cvta.to.shared.u64 t, %1; cvt.u32.u64 %0, t; }"
        : "=r"(a) : "l"(p));
    return a;
}
static __device__ __forceinline__ void cp16(uint32_t dst, const void* src) {
    asm volatile("cp.async.cg.shared.global [%0], [%1], 16;"
                 :: "r"(dst), "l"(src) : "memory");
}
#define CP_COMMIT() asm volatile("cp.async.commit_group;" ::: "memory")
#define CP_WAIT(n)  asm volatile("cp.async.wait_group %0;" :: "n"(n) : "memory")

static __device__ __forceinline__ void split_tf32(float v, uint32_t& hi, uint32_t& lo) {
    asm("cvt.rna.tf32.f32 %0, %1;" : "=r"(hi) : "f"(v));
    const float l = v - __uint_as_float(hi);
    asm("cvt.rna.tf32.f32 %0, %1;" : "=r"(lo) : "f"(l));
}
static __device__ __forceinline__ void mma8(float* c, const uint32_t* a,
                                            uint32_t b0, uint32_t b1) {
    asm volatile(
        "mma.sync.aligned.m16n8k8.row.col.f32.tf32.tf32.f32 "
        "{%0,%1,%2,%3}, {%4,%5,%6,%7}, {%8,%9}, {%0,%1,%2,%3};"
        : "+f"(c[0]), "+f"(c[1]), "+f"(c[2]), "+f"(c[3])
        : "r"(a[0]), "r"(a[1]), "r"(a[2]), "r"(a[3]), "r"(b0), "r"(b1));
}

// Pre-split weights: W[e][k] -> (tf32 hi, tf32 lo), interleaved.
__device__ uint2 g_wsplit[NE * DIM];

__global__ void split_w_kernel(const float* __restrict__ W) {
    const int i = blockIdx.x * blockDim.x + threadIdx.x;
    if (i < NE * DIM) {
        uint32_t hi, lo;
        split_tf32(W[i], hi, lo);
        g_wsplit[i] = make_uint2(hi, lo);
    }
}

__global__ __launch_bounds__(NTHR, 1)
void gating_mma(const float* __restrict__ X, const float* __restrict__ B,
                float* __restrict__ out, int voff)
{
    extern __shared__ char smem[];
    const int tid    = threadIdx.x;
    const int wid    = tid >> 5;
    const int lane   = tid & 31;
    const int qid    = lane >> 2;
    const int qt     = lane & 3;
    const int stripe = wid & 7;        // m16 stripe 0..7
    const int nhalf  = wid >> 3;       // expert half: 0 -> experts 0..31, 1 -> 32..63
    const int token0 = blockIdx.x * BT;

    const uint32_t sbase = smem_u32(smem);

    // ---- producer mapping (512 threads, 2 cp16 each per tile) ----
    const int arow = tid >> 2, aseg0 = (tid & 3) * 2;   // A: 128 rows x 8 segs(16B)
    const int wrow = tid >> 3, wseg0 = (tid & 7) * 2;   // W: 64 rows x 16 segs(16B)
    const float* agp = X + (size_t)(token0 + arow) * DIM;
    const uint2* wgp = g_wsplit + (size_t)wrow * DIM;

    auto issue_chunk = [&](int c) {
        const uint32_t ab = sbase + (uint32_t)(c & (NBUF - 1)) * BUFB;
        const uint32_t wb = ab + ABYTES;
        const float* ag = agp + c * KT;
        #pragma unroll
        for (int j = 0; j < 2; j++)
            cp16(ab + (uint32_t)arow * (ASTR * 4) + (aseg0 + j) * 16, ag + (aseg0 + j) * 4);
        const uint2* wg = wgp + c * KT;
        #pragma unroll
        for (int j = 0; j < 2; j++)
            cp16(wb + (uint32_t)wrow * (WS2 * 8) + (wseg0 + j) * 16, wg + (wseg0 + j) * 2);
    };

    float acc[4][4];
    #pragma unroll
    for (int nt = 0; nt < 4; nt++)
        #pragma unroll
        for (int j = 0; j < 4; j++) acc[nt][j] = 0.f;

    issue_chunk(0); CP_COMMIT();
    issue_chunk(1); CP_COMMIT();
    issue_chunk(2); CP_COMMIT();

    const int ar0 = (stripe * 16 + qid) * ASTR;
    const int wr0 = nhalf * 32 + qid;

    #pragma unroll 1
    for (int c = 0; c < NCH; c++) {
        CP_WAIT(2);
        __syncthreads();

        const char* buf = smem + (c & (NBUF - 1)) * BUFB;
        const float* As = (const float*)buf;
        const uint2* Ws = (const uint2*)(buf + ABYTES);

        #pragma unroll
        for (int kk = 0; kk < 4; kk++) {
            const int kc = kk * 8 + qt;

            uint32_t ah[4], al[4];
            split_tf32(As[ar0 + kc],                ah[0], al[0]);
            split_tf32(As[ar0 + 8 * ASTR + kc],     ah[1], al[1]);
            split_tf32(As[ar0 + kc + 4],            ah[2], al[2]);
            split_tf32(As[ar0 + 8 * ASTR + kc + 4], ah[3], al[3]);

            uint2 b0[4], b1[4];
            #pragma unroll
            for (int nt = 0; nt < 4; nt++) {
                const int br = (wr0 + nt * 8) * WS2 + kc;
                b0[nt] = Ws[br];
                b1[nt] = Ws[br + 4];
            }

            #pragma unroll
            for (int nt = 0; nt < 4; nt++) mma8(acc[nt], ah, b0[nt].x, b1[nt].x); // Ah*Bh
            #pragma unroll
            for (int nt = 0; nt < 4; nt++) mma8(acc[nt], ah, b0[nt].y, b1[nt].y); // Ah*Bl
            #pragma unroll
            for (int nt = 0; nt < 4; nt++) mma8(acc[nt], al, b0[nt].x, b1[nt].x); // Al*Bh
        }

        if (c + 3 < NCH) issue_chunk(c + 3);
        CP_COMMIT();   // uniform group accounting
    }

    CP_WAIT(0);
    __syncthreads();

    // ---- scores -> smem (bias fused), then per-token softmax + top-2 ----
    float* SC = (float*)smem;
    {
        const int r0 = stripe * 16 + qid, r1 = r0 + 8;
        #pragma unroll
        for (int nt = 0; nt < 4; nt++) {
            const int cb = nhalf * 32 + nt * 8 + qt * 2;
            const float b0 = __ldg(B + cb), b1 = __ldg(B + cb + 1);
            *(float2*)(SC + r0 * SCSTR + cb) = make_float2(acc[nt][0] + b0, acc[nt][1] + b1);
            *(float2*)(SC + r1 * SCSTR + cb) = make_float2(acc[nt][2] + b0, acc[nt][3] + b1);
        }
    }
    __syncthreads();

    if (tid < BT) {
        const float* row = SC + tid * SCSTR;
        float m = row[0];
        #pragma unroll
        for (int e = 1; e < NE; e++) m = fmaxf(m, row[e]);

        float se = 0.f;
        #pragma unroll
        for (int e = 0; e < NE; e++) se += __expf(row[e] - m);

        float v1 = -1e30f, v2 = -1e30f; int i1 = -1, i2 = -1;
        #pragma unroll
        for (int e = 0; e < NE; e++) {
            const float s = row[e];
            if (s > v1)      { v2 = v1; i2 = i1; v1 = s; i1 = e; }
            else if (s > v2) { v2 = s; i2 = e; }
        }

        const int g = token0 + tid;
        const float inv = 1.0f / se;
        out[g * 2 + 0]        = (float)i1;
        out[g * 2 + 1]        = (float)i2;
        out[voff + g * 2 + 0] = __expf(v1 - m) * inv;
        out[voff + g * 2 + 1] = __expf(v2 - m) * inv;
    }
}

extern "C" void kernel_launch(void* const* d_in, const int* in_sizes, int n_in,
                              void* d_out, int out_size) {
    const float* x = (const float*)d_in[0];
    const float* W = (const float*)d_in[1];
    const float* b = (const float*)d_in[2];
    float* out = (float*)d_out;

    split_w_kernel<<<(NE * DIM + 255) / 256, 256>>>(W);

    cudaFuncSetAttribute(gating_mma, cudaFuncAttributeMaxDynamicSharedMemorySize, SMEM_DYN);
    gating_mma<<<NTOK / BT, NTHR, SMEM_DYN>>>(x, b, out, out_size / 2);
}

// round 8
// speedup vs baseline: 1.7351x; 1.0001x over previous
#include <cuda_runtime.h>
#include <cstdint>
#include <math.h>

#define NTOK 16384
#define DIM  4096
#define NE   64
#define BT   128                  // tokens per CTA (M): 8 m16 stripes
#define KT   32                   // K per chunk (4 k-steps of 8)
#define NCH  (DIM / KT)           // 128
#define NBUF 4
#define NTHR 512
#define ASTR 36                   // A smem stride in floats (bank-clean)
#define WS2  36                   // W smem stride in uint2 (8*(qid%4)+2qt injective)
#define ABYTES (BT * ASTR * 4)    // 18432
#define WBYTES (NE * WS2 * 8)     // 18432
#define BUFB   (ABYTES + WBYTES)  // 36864
#define SMEM_DYN (NBUF * BUFB)    // 147456
#define SCSTR 66

static __device__ __forceinline__ uint32_t smem_u32(const void* p) {
    uint32_t a;
    asm("{ .reg .u64 t; cvta.to.shared.u64 t, %1; cvt.u32.u64 %0, t; }"
        : "=r"(a) : "l"(p));
    return a;
}
static __device__ __forceinline__ void cp16(uint32_t dst, const void* src) {
    asm volatile("cp.async.cg.shared.global [%0], [%1], 16;"
                 :: "r"(dst), "l"(src) : "memory");
}
#define CP_COMMIT() asm volatile("cp.async.commit_group;" ::: "memory")
#define CP_WAIT(n)  asm volatile("cp.async.wait_group %0;" :: "n"(n) : "memory")

static __device__ __forceinline__ void split_tf32(float v, uint32_t& hi, uint32_t& lo) {
    asm("cvt.rna.tf32.f32 %0, %1;" : "=r"(hi) : "f"(v));
    const float l = v - __uint_as_float(hi);
    asm("cvt.rna.tf32.f32 %0, %1;" : "=r"(lo) : "f"(l));
}
static __device__ __forceinline__ void mma8(float* c, const uint32_t* a,
                                            uint32_t b0, uint32_t b1) {
    asm volatile(
        "mma.sync.aligned.m16n8k8.row.col.f32.tf32.tf32.f32 "
        "{%0,%1,%2,%3}, {%4,%5,%6,%7}, {%8,%9}, {%0,%1,%2,%3};"
        : "+f"(c[0]), "+f"(c[1]), "+f"(c[2]), "+f"(c[3])
        : "r"(a[0]), "r"(a[1]), "r"(a[2]), "r"(a[3]), "r"(b0), "r"(b1));
}

// Pre-split weights: W[e][k] -> (tf32 hi, tf32 lo), interleaved.
__device__ uint2 g_wsplit[NE * DIM];

__global__ void split_w_kernel(const float* __restrict__ W) {
    const int i = blockIdx.x * blockDim.x + threadIdx.x;
    if (i < NE * DIM) {
        uint32_t hi, lo;
        split_tf32(W[i], hi, lo);
        g_wsplit[i] = make_uint2(hi, lo);
    }
}

__global__ __launch_bounds__(NTHR, 1)
void gating_mma(const float* __restrict__ X, const float* __restrict__ B,
                float* __restrict__ out, int voff)
{
    extern __shared__ char smem[];
    const int tid    = threadIdx.x;
    const int wid    = tid >> 5;
    const int lane   = tid & 31;
    const int qid    = lane >> 2;
    const int qt     = lane & 3;
    const int stripe = wid & 7;        // m16 stripe 0..7
    const int nhalf  = wid >> 3;       // expert half: 0 -> experts 0..31, 1 -> 32..63
    const int token0 = blockIdx.x * BT;

    const uint32_t sbase = smem_u32(smem);

    // ---- producer mapping (512 threads, 2 cp16 each per tile) ----
    const int arow = tid >> 2, aseg0 = (tid & 3) * 2;   // A: 128 rows x 8 segs(16B)
    const int wrow = tid >> 3, wseg0 = (tid & 7) * 2;   // W: 64 rows x 16 segs(16B)
    const float* agp = X + (size_t)(token0 + arow) * DIM;
    const uint2* wgp = g_wsplit + (size_t)wrow * DIM;

    auto issue_chunk = [&](int c) {
        const uint32_t ab = sbase + (uint32_t)(c & (NBUF - 1)) * BUFB;
        const uint32_t wb = ab + ABYTES;
        const float* ag = agp + c * KT;
        #pragma unroll
        for (int j = 0; j < 2; j++)
            cp16(ab + (uint32_t)arow * (ASTR * 4) + (aseg0 + j) * 16, ag + (aseg0 + j) * 4);
        const uint2* wg = wgp + c * KT;
        #pragma unroll
        for (int j = 0; j < 2; j++)
            cp16(wb + (uint32_t)wrow * (WS2 * 8) + (wseg0 + j) * 16, wg + (wseg0 + j) * 2);
    };

    float acc[4][4];
    #pragma unroll
    for (int nt = 0; nt < 4; nt++)
        #pragma unroll
        for (int j = 0; j < 4; j++) acc[nt][j] = 0.f;

    issue_chunk(0); CP_COMMIT();
    issue_chunk(1); CP_COMMIT();
    issue_chunk(2); CP_COMMIT();

    const int ar0 = (stripe * 16 + qid) * ASTR;
    const int wr0 = nhalf * 32 + qid;

    #pragma unroll 1
    for (int c = 0; c < NCH; c++) {
        CP_WAIT(2);
        __syncthreads();

        const char* buf = smem + (c & (NBUF - 1)) * BUFB;
        const float* As = (const float*)buf;
        const uint2* Ws = (const uint2*)(buf + ABYTES);

        #pragma unroll
        for (int kk = 0; kk < 4; kk++) {
            const int kc = kk * 8 + qt;

            uint32_t ah[4], al[4];
            split_tf32(As[ar0 + kc],                ah[0], al[0]);
            split_tf32(As[ar0 + 8 * ASTR + kc],     ah[1], al[1]);
            split_tf32(As[ar0 + kc + 4],            ah[2], al[2]);
            split_tf32(As[ar0 + 8 * ASTR + kc + 4], ah[3], al[3]);

            uint2 b0[4], b1[4];
            #pragma unroll
            for (int nt = 0; nt < 4; nt++) {
                const int br = (wr0 + nt * 8) * WS2 + kc;
                b0[nt] = Ws[br];
                b1[nt] = Ws[br + 4];
            }

            #pragma unroll
            for (int nt = 0; nt < 4; nt++) mma8(acc[nt], ah, b0[nt].x, b1[nt].x); // Ah*Bh
            #pragma unroll
            for (int nt = 0; nt < 4; nt++) mma8(acc[nt], ah, b0[nt].y, b1[nt].y); // Ah*Bl
            #pragma unroll
            for (int nt = 0; nt < 4; nt++) mma8(acc[nt], al, b0[nt].x, b1[nt].x); // Al*Bh
        }

        if (c + 3 < NCH) issue_chunk(c + 3);
        CP_COMMIT();   // uniform group accounting
    }

    CP_WAIT(0);
    __syncthreads();

    // ---- scores -> smem (bias fused), then per-token softmax + top-2 ----
    float* SC = (float*)smem;
    {
        const int r0 = stripe * 16 + qid, r1 = r0 + 8;
        #pragma unroll
        for (int nt = 0; nt < 4; nt++) {
            const int cb = nhalf * 32 + nt * 8 + qt * 2;
            const float b0 = __ldg(B + cb), b1 = __ldg(B + cb + 1);
            *(float2*)(SC + r0 * SCSTR + cb) = make_float2(acc[nt][0] + b0, acc[nt][1] + b1);
            *(float2*)(SC + r1 * SCSTR + cb) = make_float2(acc[nt][2] + b0, acc[nt][3] + b1);
        }
    }
    __syncthreads();

    if (tid < BT) {
        const float* row = SC + tid * SCSTR;
        float m = row[0];
        #pragma unroll
        for (int e = 1; e < NE; e++) m = fmaxf(m, row[e]);

        float se = 0.f;
        #pragma unroll
        for (int e = 0; e < NE; e++) se += __expf(row[e] - m);

        float v1 = -1e30f, v2 = -1e30f; int i1 = -1, i2 = -1;
        #pragma unroll
        for (int e = 0; e < NE; e++) {
            const float s = row[e];
            if (s > v1)      { v2 = v1; i2 = i1; v1 = s; i1 = e; }
            else if (s > v2) { v2 = s; i2 = e; }
        }

        const int g = token0 + tid;
        const float inv = 1.0f / se;
        out[g * 2 + 0]        = (float)i1;
        out[g * 2 + 1]        = (float)i2;
        out[voff + g * 2 + 0] = __expf(v1 - m) * inv;
        out[voff + g * 2 + 1] = __expf(v2 - m) * inv;
    }
}

extern "C" void kernel_launch(void* const* d_in, const int* in_sizes, int n_in,
                              void* d_out, int out_size) {
    const float* x = (const float*)d_in[0];
    const float* W = (const float*)d_in[1];
    const float* b = (const float*)d_in[2];
    float* out = (float*)d_out;

    split_w_kernel<<<(NE * DIM + 255) / 256, 256>>>(W);

    cudaFuncSetAttribute(gating_mma, cudaFuncAttributeMaxDynamicSharedMemorySize, SMEM_DYN);
    gating_mma<<<NTOK / BT, NTHR, SMEM_DYN>>>(x, b, out, out_size / 2);
}

// round 9
// speedup vs baseline: 1.9342x; 1.1147x over previous
#include <cuda_runtime.h>
#include <cstdint>
#include <math.h>

#define NTOK 16384
#define DIM  4096
#define NE   64
#define BT   128                  // tokens per CTA (M): 8 m16 stripes
#define KT   32                   // K per chunk (4 k-steps of 8)
#define NCH  (DIM / KT)           // 128
#define NBUF 4
#define NTHR 1024
#define ASTR 36                   // A smem stride in floats (bank-clean)
#define WS2  36                   // W smem stride in uint2
#define ABYTES (BT * ASTR * 4)    // 18432
#define WBYTES (NE * WS2 * 8)     // 18432
#define BUFB   (ABYTES + WBYTES)  // 36864
#define SMEM_DYN (NBUF * BUFB)    // 147456
#define SCSTR 66

static __device__ __forceinline__ uint32_t smem_u32(const void* p) {
    uint32_t a;
    asm("{ .reg .u64 t; cvta.to.shared.u64 t, %1; cvt.u32.u64 %0, t; }"
        : "=r"(a) : "l"(p));
    return a;
}
static __device__ __forceinline__ void cp16(uint32_t dst, const void* src) {
    asm volatile("cp.async.cg.shared.global [%0], [%1], 16;"
                 :: "r"(dst), "l"(src) : "memory");
}
#define CP_COMMIT() asm volatile("cp.async.commit_group;" ::: "memory")
#define CP_WAIT(n)  asm volatile("cp.async.wait_group %0;" :: "n"(n) : "memory")

// rna split for the (offline) W path — max accuracy there.
static __device__ __forceinline__ void split_tf32(float v, uint32_t& hi, uint32_t& lo) {
    asm("cvt.rna.tf32.f32 %0, %1;" : "=r"(hi) : "f"(v));
    const float l = v - __uint_as_float(hi);
    asm("cvt.rna.tf32.f32 %0, %1;" : "=r"(lo) : "f"(l));
}
// cheap split for the A path: AND-truncate hi (exact in tf32), raw residual lo
// (tensor HW reads only tf32 bits of the register; truncation error ~2^-23).
static __device__ __forceinline__ void split2(float v, uint32_t& hi, uint32_t& lo) {
    hi = __float_as_uint(v) & 0xffffe000u;
    lo = __float_as_uint(v - __uint_as_float(hi));
}
static __device__ __forceinline__ void mma8(float* c, const uint32_t* a,
                                            uint32_t b0, uint32_t b1) {
    asm volatile(
        "mma.sync.aligned.m16n8k8.row.col.f32.tf32.tf32.f32 "
        "{%0,%1,%2,%3}, {%4,%5,%6,%7}, {%8,%9}, {%0,%1,%2,%3};"
        : "+f"(c[0]), "+f"(c[1]), "+f"(c[2]), "+f"(c[3])
        : "r"(a[0]), "r"(a[1]), "r"(a[2]), "r"(a[3]), "r"(b0), "r"(b1));
}

// Pre-split weights: W[e][k] -> (tf32 hi, tf32 lo), interleaved.
__device__ uint2 g_wsplit[NE * DIM];

__global__ void split_w_kernel(const float* __restrict__ W) {
    const int i = blockIdx.x * blockDim.x + threadIdx.x;
    if (i < NE * DIM) {
        uint32_t hi, lo;
        split_tf32(W[i], hi, lo);
        g_wsplit[i] = make_uint2(hi, lo);
    }
}

__global__ __launch_bounds__(NTHR, 1)
void gating_mma(const float* __restrict__ X, const float* __restrict__ B,
                float* __restrict__ out, int voff)
{
    extern __shared__ char smem[];
    const int tid    = threadIdx.x;
    const int wid    = tid >> 5;
    const int lane   = tid & 31;
    const int qid    = lane >> 2;
    const int qt     = lane & 3;
    const int stripe = wid & 7;        // m16 stripe 0..7
    const int nquad  = wid >> 3;       // expert quadrant: experts [nquad*16, nquad*16+16)
    const int token0 = blockIdx.x * BT;

    const uint32_t sbase = smem_u32(smem);

    // ---- producer mapping (1024 threads, 1 cp16 per tile each) ----
    const int arow = tid >> 3, aseg = tid & 7;     // A: 128 rows x 8 segs(16B)
    const int wrow = tid >> 4, wseg = tid & 15;    // W: 64 rows x 16 segs(16B)
    const float* agp = X + (size_t)(token0 + arow) * DIM + aseg * 4;
    const uint2* wgp = g_wsplit + (size_t)wrow * DIM + wseg * 2;
    const uint32_t aoff = (uint32_t)arow * (ASTR * 4) + aseg * 16;
    const uint32_t woff = ABYTES + (uint32_t)wrow * (WS2 * 8) + wseg * 16;

    auto issue_chunk = [&](int c) {
        const uint32_t bb = sbase + (uint32_t)(c & (NBUF - 1)) * BUFB;
        cp16(bb + aoff, agp + c * KT);
        cp16(bb + woff, wgp + c * KT);
    };

    float acch[2][4], accl[2][4];
    #pragma unroll
    for (int nt = 0; nt < 2; nt++)
        #pragma unroll
        for (int j = 0; j < 4; j++) { acch[nt][j] = 0.f; accl[nt][j] = 0.f; }

    issue_chunk(0); CP_COMMIT();
    issue_chunk(1); CP_COMMIT();
    issue_chunk(2); CP_COMMIT();

    const int ar0 = (stripe * 16 + qid) * ASTR;
    const int wr0 = nquad * 16 + qid;

    #pragma unroll 1
    for (int c = 0; c < NCH; c++) {
        CP_WAIT(2);
        __syncthreads();

        const char* buf = smem + (c & (NBUF - 1)) * BUFB;
        const float* As = (const float*)buf;
        const uint2* Ws = (const uint2*)(buf + ABYTES);

        #pragma unroll
        for (int kk = 0; kk < 4; kk++) {
            const int kc = kk * 8 + qt;

            uint32_t ah[4], al[4];
            split2(As[ar0 + kc],                ah[0], al[0]);
            split2(As[ar0 + 8 * ASTR + kc],     ah[1], al[1]);
            split2(As[ar0 + kc + 4],            ah[2], al[2]);
            split2(As[ar0 + 8 * ASTR + kc + 4], ah[3], al[3]);

            uint2 b0[2], b1[2];
            #pragma unroll
            for (int nt = 0; nt < 2; nt++) {
                const int br = (wr0 + nt * 8) * WS2 + kc;
                b0[nt] = Ws[br];
                b1[nt] = Ws[br + 4];
            }

            #pragma unroll
            for (int nt = 0; nt < 2; nt++) {
                mma8(acch[nt], ah, b0[nt].x, b1[nt].x);   // Ah*Bh
                mma8(accl[nt], ah, b0[nt].y, b1[nt].y);   // Ah*Bl
                mma8(accl[nt], al, b0[nt].x, b1[nt].x);   // Al*Bh
            }
        }

        if (c + 3 < NCH) issue_chunk(c + 3);
        CP_COMMIT();   // uniform group accounting
    }

    CP_WAIT(0);
    __syncthreads();

    // ---- scores -> smem (bias fused), then per-token softmax + top-2 ----
    float* SC = (float*)smem;
    {
        const int r0 = stripe * 16 + qid, r1 = r0 + 8;
        #pragma unroll
        for (int nt = 0; nt < 2; nt++) {
            const int cb = nquad * 16 + nt * 8 + qt * 2;
            const float b0 = __ldg(B + cb), b1 = __ldg(B + cb + 1);
            *(float2*)(SC + r0 * SCSTR + cb) =
                make_float2(acch[nt][0] + accl[nt][0] + b0, acch[nt][1] + accl[nt][1] + b1);
            *(float2*)(SC + r1 * SCSTR + cb) =
                make_float2(acch[nt][2] + accl[nt][2] + b0, acch[nt][3] + accl[nt][3] + b1);
        }
    }
    __syncthreads();

    if (tid < BT) {
        const float* row = SC + tid * SCSTR;
        float m = row[0];
        #pragma unroll
        for (int e = 1; e < NE; e++) m = fmaxf(m, row[e]);

        float se = 0.f;
        #pragma unroll
        for (int e = 0; e < NE; e++) se += __expf(row[e] - m);

        float v1 = -1e30f, v2 = -1e30f; int i1 = -1, i2 = -1;
        #pragma unroll
        for (int e = 0; e < NE; e++) {
            const float s = row[e];
            if (s > v1)      { v2 = v1; i2 = i1; v1 = s; i1 = e; }
            else if (s > v2) { v2 = s; i2 = e; }
        }

        const int g = token0 + tid;
        const float inv = 1.0f / se;
        out[g * 2 + 0]        = (float)i1;
        out[g * 2 + 1]        = (float)i2;
        out[voff + g * 2 + 0] = __expf(v1 - m) * inv;
        out[voff + g * 2 + 1] = __expf(v2 - m) * inv;
    }
}

extern "C" void kernel_launch(void* const* d_in, const int* in_sizes, int n_in,
                              void* d_out, int out_size) {
    const float* x = (const float*)d_in[0];
    const float* W = (const float*)d_in[1];
    const float* b = (const float*)d_in[2];
    float* out = (float*)d_out;

    split_w_kernel<<<(NE * DIM + 255) / 256, 256>>>(W);

    cudaFuncSetAttribute(gating_mma, cudaFuncAttributeMaxDynamicSharedMemorySize, SMEM_DYN);
    gating_mma<<<NTOK / BT, NTHR, SMEM_DYN>>>(x, b, out, out_size / 2);
}

// round 10
// speedup vs baseline: 2.8817x; 1.4899x over previous
#include <cuda_runtime.h>
#include <cuda_fp16.h>
#include <cstdint>
#include <math.h>

#define NTOK 16384
#define DIM  4096
#define NE   64
#define BT   128                  // tokens per CTA (M): 8 m16 stripes
#define KT   32                   // K per chunk (2 k-steps of 16)
#define NCH  (DIM / KT)           // 128
#define NBUF 4
#define NTHR 1024
#define ASTR 40                   // A smem stride in floats (LDS.64 bank-clean)
#define WSP  36                   // W smem stride in f16x2 pairs (4*row+qt injective)
#define ABYTES (BT * ASTR * 4)    // 20480
#define WROWB  (WSP * 4)          // 144 B per W row per array
#define WBYTES (NE * WROWB)       // 9216 per array (hi / lo)
#define BUFB   (ABYTES + 2 * WBYTES)  // 38912
#define SMEM_DYN (NBUF * BUFB)        // 155648
#define SCSTR 66

static __device__ __forceinline__ uint32_t smem_u32(const void* p) {
    uint32_t a;
    asm("{ .reg .u64 t; cvta.to.shared.u64 t, %1; cvt.u32.u64 %0, t; }"
        : "=r"(a) : "l"(p));
    return a;
}
static __device__ __forceinline__ void cp16(uint32_t dst, const void* src) {
    asm volatile("cp.async.cg.shared.global [%0], [%1], 16;"
                 :: "r"(dst), "l"(src) : "memory");
}
#define CP_COMMIT() asm volatile("cp.async.commit_group;" ::: "memory")
#define CP_WAIT(n)  asm volatile("cp.async.wait_group %0;" :: "n"(n) : "memory")

// A split: hi = rz-f16 pack (== mantissa-mask in normal range), lo = rz-f16(x - mask(x)).
static __device__ __forceinline__ void split_pair(float f0, float f1,
                                                  uint32_t& hi2, uint32_t& lo2) {
    asm("cvt.rz.f16x2.f32 %0, %1, %2;" : "=r"(hi2) : "f"(f1), "f"(f0));
    const float m0 = __uint_as_float(__float_as_uint(f0) & 0xffffe000u);
    const float m1 = __uint_as_float(__float_as_uint(f1) & 0xffffe000u);
    const float r0 = f0 - m0, r1 = f1 - m1;
    asm("cvt.rz.f16x2.f32 %0, %1, %2;" : "=r"(lo2) : "f"(r1), "f"(r0));
}
static __device__ __forceinline__ void mma16(float* c, const uint32_t* a,
                                             uint32_t b0, uint32_t b1) {
    asm volatile(
        "mma.sync.aligned.m16n8k16.row.col.f32.f16.f16.f32 "
        "{%0,%1,%2,%3}, {%4,%5,%6,%7}, {%8,%9}, {%0,%1,%2,%3};"
        : "+f"(c[0]), "+f"(c[1]), "+f"(c[2]), "+f"(c[3])
        : "r"(a[0]), "r"(a[1]), "r"(a[2]), "r"(a[3]), "r"(b0), "r"(b1));
}

// Pre-split weights: W -> f16 hi + f16 lo (rn split, done once).
__device__ __half g_wh[NE * DIM];
__device__ __half g_wl[NE * DIM];

__global__ void split_w_kernel(const float* __restrict__ W) {
    const int i = blockIdx.x * blockDim.x + threadIdx.x;
    if (i < NE * DIM) {
        const float w = W[i];
        const __half h = __float2half_rn(w);
        g_wh[i] = h;
        g_wl[i] = __float2half_rn(w - __half2float(h));
    }
}

__global__ __launch_bounds__(NTHR, 1)
void gating_mma(const float* __restrict__ X, const float* __restrict__ B,
                float* __restrict__ out, int voff)
{
    extern __shared__ char smem[];
    const int tid    = threadIdx.x;
    const int wid    = tid >> 5;
    const int lane   = tid & 31;
    const int qid    = lane >> 2;
    const int qt     = lane & 3;
    const int stripe = wid & 7;        // m16 stripe 0..7
    const int nquad  = wid >> 3;       // experts [nquad*16, nquad*16+16)
    const int token0 = blockIdx.x * BT;

    const uint32_t sbase = smem_u32(smem);

    // ---- producers ----
    // A: 128 rows x 8 segs(16B) -> 1024 threads, 1 cp16 each
    const int arow = tid >> 3, aseg = tid & 7;
    const float* agp = X + (size_t)(token0 + arow) * DIM + aseg * 4;
    const uint32_t aoff = (uint32_t)arow * (ASTR * 4) + aseg * 16;
    // W: 64 rows x (4 hi + 4 lo) segs(16B) -> threads < 512, 1 cp16 each
    const int wrow = tid >> 3, wsel = tid & 7;           // valid for tid<512
    const int wseg = wsel & 3;
    const bool whalf_lo = (wsel & 4) != 0;
    const __half* wgp = (whalf_lo ? g_wl : g_wh) + (size_t)wrow * DIM + wseg * 8;
    const uint32_t woff = ABYTES + (whalf_lo ? WBYTES : 0u)
                        + (uint32_t)wrow * WROWB + wseg * 16;

    auto issue_chunk = [&](int c) {
        const uint32_t bb = sbase + (uint32_t)(c & (NBUF - 1)) * BUFB;
        cp16(bb + aoff, agp + c * KT);
        if (tid < 512) cp16(bb + woff, wgp + c * KT);
    };

    float acch[2][4], accl[2][4];
    #pragma unroll
    for (int nt = 0; nt < 2; nt++)
        #pragma unroll
        for (int j = 0; j < 4; j++) { acch[nt][j] = 0.f; accl[nt][j] = 0.f; }

    issue_chunk(0); CP_COMMIT();
    issue_chunk(1); CP_COMMIT();
    issue_chunk(2); CP_COMMIT();

    const int ar0 = (stripe * 16 + qid) * ASTR;
    const int wr0 = nquad * 16 + qid;

    #pragma unroll 1
    for (int c = 0; c < NCH; c++) {
        CP_WAIT(2);
        __syncthreads();

        const char* buf = smem + (c & (NBUF - 1)) * BUFB;
        const float* As = (const float*)buf;
        const uint32_t* Wh = (const uint32_t*)(buf + ABYTES);
        const uint32_t* Wl = (const uint32_t*)(buf + ABYTES + WBYTES);

        #pragma unroll
        for (int ks = 0; ks < 2; ks++) {           // two k16 steps
            const int kb = ks * 16;

            // A fragment: rows {qid, qid+8}, k pairs {2qt, 2qt+8}
            const float2 a00 = *(const float2*)&As[ar0 + kb + 2 * qt];
            const float2 a10 = *(const float2*)&As[ar0 + 8 * ASTR + kb + 2 * qt];
            const float2 a01 = *(const float2*)&As[ar0 + kb + 2 * qt + 8];
            const float2 a11 = *(const float2*)&As[ar0 + 8 * ASTR + kb + 2 * qt + 8];
            uint32_t ah[4], al[4];
            split_pair(a00.x, a00.y, ah[0], al[0]);
            split_pair(a10.x, a10.y, ah[1], al[1]);
            split_pair(a01.x, a01.y, ah[2], al[2]);
            split_pair(a11.x, a11.y, ah[3], al[3]);

            // B fragments (f16x2 pair index within row: ks*8 + {qt, qt+4})
            #pragma unroll
            for (int nt = 0; nt < 2; nt++) {
                const int br = (wr0 + nt * 8) * WSP + ks * 8 + qt;
                const uint32_t b0h = Wh[br], b1h = Wh[br + 4];
                const uint32_t b0l = Wl[br], b1l = Wl[br + 4];
                mma16(acch[nt], ah, b0h, b1h);     // Ah*Bh
                mma16(accl[nt], ah, b0l, b1l);     // Ah*Bl
                mma16(accl[nt], al, b0h, b1h);     // Al*Bh
            }
        }

        if (c + 3 < NCH) issue_chunk(c + 3);
        CP_COMMIT();   // uniform group accounting
    }

    CP_WAIT(0);
    __syncthreads();

    // ---- scores -> smem (bias fused), then per-token softmax + top-2 ----
    float* SC = (float*)smem;
    {
        const int r0 = stripe * 16 + qid, r1 = r0 + 8;
        #pragma unroll
        for (int nt = 0; nt < 2; nt++) {
            const int cb = nquad * 16 + nt * 8 + qt * 2;
            const float b0 = __ldg(B + cb), b1 = __ldg(B + cb + 1);
            *(float2*)(SC + r0 * SCSTR + cb) =
                make_float2(acch[nt][0] + accl[nt][0] + b0, acch[nt][1] + accl[nt][1] + b1);
            *(float2*)(SC + r1 * SCSTR + cb) =
                make_float2(acch[nt][2] + accl[nt][2] + b0, acch[nt][3] + accl[nt][3] + b1);
        }
    }
    __syncthreads();

    if (tid < BT) {
        const float* row = SC + tid * SCSTR;
        float m = row[0];
        #pragma unroll
        for (int e = 1; e < NE; e++) m = fmaxf(m, row[e]);

        float se = 0.f;
        #pragma unroll
        for (int e = 0; e < NE; e++) se += __expf(row[e] - m);

        float v1 = -1e30f, v2 = -1e30f; int i1 = -1, i2 = -1;
        #pragma unroll
        for (int e = 0; e < NE; e++) {
            const float s = row[e];
            if (s > v1)      { v2 = v1; i2 = i1; v1 = s; i1 = e; }
            else if (s > v2) { v2 = s; i2 = e; }
        }

        const int g = token0 + tid;
        const float inv = 1.0f / se;
        out[g * 2 + 0]        = (float)i1;
        out[g * 2 + 1]        = (float)i2;
        out[voff + g * 2 + 0] = __expf(v1 - m) * inv;
        out[voff + g * 2 + 1] = __expf(v2 - m) * inv;
    }
}

extern "C" void kernel_launch(void* const* d_in, const int* in_sizes, int n_in,
                              void* d_out, int out_size) {
    const float* x = (const float*)d_in[0];
    const float* W = (const float*)d_in[1];
    const float* b = (const float*)d_in[2];
    float* out = (float*)d_out;

    split_w_kernel<<<(NE * DIM + 255) / 256, 256>>>(W);

    cudaFuncSetAttribute(gating_mma, cudaFuncAttributeMaxDynamicSharedMemorySize, SMEM_DYN);
    gating_mma<<<NTOK / BT, NTHR, SMEM_DYN>>>(x, b, out, out_size / 2);
}

// round 11
// speedup vs baseline: 3.0127x; 1.0455x over previous
#include <cuda_runtime.h>
#include <cuda_fp16.h>
#include <cstdint>
#include <math.h>

#define NTOK 16384
#define DIM  4096
#define NE   64
#define BT   128                  // tokens per CTA (M): 8 m16 stripes
#define KT   32                   // K per chunk (2 k16 halves, split across warps)
#define NCH  (DIM / KT)           // 128
#define NBUF 4
#define NTHR 1024
#define ASTR 40                   // A smem stride in floats (LDS.64 bank-clean)
#define WSP  36                   // W smem stride in f16x2 pairs (4*qid+qt injective)
#define ABYTES (BT * ASTR * 4)    // 20480
#define WROWB  (WSP * 4)          // 144 B per W row per array
#define WBYTES (NE * WROWB)       // 9216 per array (hi / lo)
#define BUFB   (ABYTES + 2 * WBYTES)  // 38912
#define SMEM_DYN (NBUF * BUFB)        // 155648
#define SCSTR 66

static __device__ __forceinline__ uint32_t smem_u32(const void* p) {
    uint32_t a;
    asm("{ .reg .u64 t; cvta.to.shared.u64 t, %1; cvt.u32.u64 %0, t; }"
        : "=r"(a) : "l"(p));
    return a;
}
static __device__ __forceinline__ void cp16(uint32_t dst, const void* src) {
    asm volatile("cp.async.cg.shared.global [%0], [%1], 16;"
                 :: "r"(dst), "l"(src) : "memory");
}
#define CP_COMMIT() asm volatile("cp.async.commit_group;" ::: "memory")
#define CP_WAIT(n)  asm volatile("cp.async.wait_group %0;" :: "n"(n) : "memory")

// A split: hi = rz-f16 pack (== mantissa-mask in normal range), lo = rz-f16(x - mask(x)).
static __device__ __forceinline__ void split_pair(float f0, float f1,
                                                  uint32_t& hi2, uint32_t& lo2) {
    asm("cvt.rz.f16x2.f32 %0, %1, %2;" : "=r"(hi2) : "f"(f1), "f"(f0));
    const float m0 = __uint_as_float(__float_as_uint(f0) & 0xffffe000u);
    const float m1 = __uint_as_float(__float_as_uint(f1) & 0xffffe000u);
    const float r0 = f0 - m0, r1 = f1 - m1;
    asm("cvt.rz.f16x2.f32 %0, %1, %2;" : "=r"(lo2) : "f"(r1), "f"(r0));
}
static __device__ __forceinline__ void mma16(float* c, const uint32_t* a,
                                             uint32_t b0, uint32_t b1) {
    asm volatile(
        "mma.sync.aligned.m16n8k16.row.col.f32.f16.f16.f32 "
        "{%0,%1,%2,%3}, {%4,%5,%6,%7}, {%8,%9}, {%0,%1,%2,%3};"
        : "+f"(c[0]), "+f"(c[1]), "+f"(c[2]), "+f"(c[3])
        : "r"(a[0]), "r"(a[1]), "r"(a[2]), "r"(a[3]), "r"(b0), "r"(b1));
}

// Pre-split weights: W -> f16 hi + f16 lo (rn split, done once).
__device__ __half g_wh[NE * DIM];
__device__ __half g_wl[NE * DIM];

__global__ void split_w_kernel(const float* __restrict__ W) {
    const int i = blockIdx.x * blockDim.x + threadIdx.x;
    if (i < NE * DIM) {
        const float w = W[i];
        const __half h = __float2half_rn(w);
        g_wh[i] = h;
        g_wl[i] = __float2half_rn(w - __half2float(h));
    }
}

__global__ __launch_bounds__(NTHR, 1)
void gating_mma(const float* __restrict__ X, const float* __restrict__ B,
                float* __restrict__ out, int voff)
{
    extern __shared__ char smem[];
    const int tid    = threadIdx.x;
    const int wid    = tid >> 5;
    const int lane   = tid & 31;
    const int qid    = lane >> 2;
    const int qt     = lane & 3;
    const int stripe = wid & 7;          // m16 stripe 0..7
    const int nhalf  = (wid >> 3) & 1;   // experts [nhalf*32, +32)
    const int khalf  = wid >> 4;         // k16 half within each chunk
    const int token0 = blockIdx.x * BT;

    const uint32_t sbase = smem_u32(smem);

    // ---- producers ----
    // A: 128 rows x 8 segs(16B) -> 1024 threads, 1 cp16 each
    const int arow = tid >> 3, aseg = tid & 7;
    const float* agp = X + (size_t)(token0 + arow) * DIM + aseg * 4;
    const uint32_t aoff = (uint32_t)arow * (ASTR * 4) + aseg * 16;
    // W: 64 rows x (4 hi + 4 lo) segs(16B) -> threads < 512, 1 cp16 each
    const int wrow = tid >> 3, wsel = tid & 7;           // valid for tid<512
    const int wseg = wsel & 3;
    const bool whalf_lo = (wsel & 4) != 0;
    const __half* wgp = (whalf_lo ? g_wl : g_wh) + (size_t)wrow * DIM + wseg * 8;
    const uint32_t woff = ABYTES + (whalf_lo ? WBYTES : 0u)
                        + (uint32_t)wrow * WROWB + wseg * 16;

    auto issue_chunk = [&](int c) {
        const uint32_t bb = sbase + (uint32_t)(c & (NBUF - 1)) * BUFB;
        cp16(bb + aoff, agp + c * KT);
        if (tid < 512) cp16(bb + woff, wgp + c * KT);
    };

    float acc[4][4];
    #pragma unroll
    for (int nt = 0; nt < 4; nt++)
        #pragma unroll
        for (int j = 0; j < 4; j++) acc[nt][j] = 0.f;

    issue_chunk(0); CP_COMMIT();
    issue_chunk(1); CP_COMMIT();
    issue_chunk(2); CP_COMMIT();

    const int ar0 = (stripe * 16 + qid) * ASTR + khalf * 16;
    const int wr0 = nhalf * 32 + qid;
    const int bp0 = khalf * 8 + qt;

    #pragma unroll 1
    for (int c = 0; c < NCH; c++) {
        CP_WAIT(2);
        __syncthreads();

        const char* buf = smem + (c & (NBUF - 1)) * BUFB;
        const float* As = (const float*)buf;
        const uint32_t* Wh = (const uint32_t*)(buf + ABYTES);
        const uint32_t* Wl = (const uint32_t*)(buf + ABYTES + WBYTES);

        // A fragment: rows {qid, qid+8}, k (within k16 half) pairs {2qt, 2qt+8}
        const float2 a00 = *(const float2*)&As[ar0 + 2 * qt];
        const float2 a10 = *(const float2*)&As[ar0 + 8 * ASTR + 2 * qt];
        const float2 a01 = *(const float2*)&As[ar0 + 2 * qt + 8];
        const float2 a11 = *(const float2*)&As[ar0 + 8 * ASTR + 2 * qt + 8];
        uint32_t ah[4], al[4];
        split_pair(a00.x, a00.y, ah[0], al[0]);
        split_pair(a10.x, a10.y, ah[1], al[1]);
        split_pair(a01.x, a01.y, ah[2], al[2]);
        split_pair(a11.x, a11.y, ah[3], al[3]);

        // B fragments: 4 n8 tiles of this warp's 32-expert half
        uint32_t b0h[4], b1h[4], b0l[4], b1l[4];
        #pragma unroll
        for (int nt = 0; nt < 4; nt++) {
            const int br = (wr0 + nt * 8) * WSP + bp0;
            b0h[nt] = Wh[br]; b1h[nt] = Wh[br + 4];
            b0l[nt] = Wl[br]; b1l[nt] = Wl[br + 4];
        }

        #pragma unroll
        for (int nt = 0; nt < 4; nt++) mma16(acc[nt], ah, b0h[nt], b1h[nt]); // Ah*Bh
        #pragma unroll
        for (int nt = 0; nt < 4; nt++) mma16(acc[nt], ah, b0l[nt], b1l[nt]); // Ah*Bl
        #pragma unroll
        for (int nt = 0; nt < 4; nt++) mma16(acc[nt], al, b0h[nt], b1h[nt]); // Al*Bh

        if (c + 3 < NCH) issue_chunk(c + 3);
        CP_COMMIT();   // uniform group accounting
    }

    CP_WAIT(0);
    __syncthreads();

    // ---- scores -> two smem banks (khalf partials), bias fused into bank 0 ----
    float* SC = (float*)smem;
    {
        float* SCk = SC + khalf * (BT * SCSTR);
        const int r0 = stripe * 16 + qid, r1 = r0 + 8;
        #pragma unroll
        for (int nt = 0; nt < 4; nt++) {
            const int cb = nhalf * 32 + nt * 8 + qt * 2;
            const float b0 = khalf ? 0.f : __ldg(B + cb);
            const float b1 = khalf ? 0.f : __ldg(B + cb + 1);
            *(float2*)(SCk + r0 * SCSTR + cb) = make_float2(acc[nt][0] + b0, acc[nt][1] + b1);
            *(float2*)(SCk + r1 * SCSTR + cb) = make_float2(acc[nt][2] + b0, acc[nt][3] + b1);
        }
    }
    __syncthreads();

    if (tid < BT) {
        const float* row0 = SC + tid * SCSTR;
        const float* row1 = row0 + BT * SCSTR;

        float sc[NE];
        #pragma unroll
        for (int e = 0; e < NE; e++) sc[e] = row0[e] + row1[e];

        float m = sc[0];
        #pragma unroll
        for (int e = 1; e < NE; e++) m = fmaxf(m, sc[e]);

        float se = 0.f;
        #pragma unroll
        for (int e = 0; e < NE; e++) se += __expf(sc[e] - m);

        float v1 = -1e30f, v2 = -1e30f; int i1 = -1, i2 = -1;
        #pragma unroll
        for (int e = 0; e < NE; e++) {
            const float s = sc[e];
            if (s > v1)      { v2 = v1; i2 = i1; v1 = s; i1 = e; }
            else if (s > v2) { v2 = s; i2 = e; }
        }

        const int g = token0 + tid;
        const float inv = 1.0f / se;
        out[g * 2 + 0]        = (float)i1;
        out[g * 2 + 1]        = (float)i2;
        out[voff + g * 2 + 0] = __expf(v1 - m) * inv;
        out[voff + g * 2 + 1] = __expf(v2 - m) * inv;
    }
}

extern "C" void kernel_launch(void* const* d_in, const int* in_sizes, int n_in,
                              void* d_out, int out_size) {
    const float* x = (const float*)d_in[0];
    const float* W = (const float*)d_in[1];
    const float* b = (const float*)d_in[2];
    float* out = (float*)d_out;

    split_w_kernel<<<(NE * DIM + 255) / 256, 256>>>(W);

    cudaFuncSetAttribute(gating_mma, cudaFuncAttributeMaxDynamicSharedMemorySize, SMEM_DYN);
    gating_mma<<<NTOK / BT, NTHR, SMEM_DYN>>>(x, b, out, out_size / 2);
}

// round 12
// speedup vs baseline: 3.0884x; 1.0252x over previous
#include <cuda_runtime.h>
#include <cuda_fp16.h>
#include <cstdint>
#include <math.h>

#define NTOK 16384
#define DIM  4096
#define NE   64
#define BT   128                  // tokens per CTA (M): 4 m32 stripes
#define KT   32                   // K per chunk (2 k16 halves, split across warps)
#define NCH  (DIM / KT)           // 128
#define NBUF 4
#define NTHR 512
#define ASTR 40                   // A smem stride in floats (LDS.64 bank-clean)
#define ABYTES (BT * ASTR * 4)    // 20480
// packed W tile: [arr 2][nhalf 2][qid 8][kpair 16 x 4B x 4nt + 64B pad] = 2*2*8*320
#define WQSTR  320                // per-(nhalf,qid) stride in bytes (bank-clean LDS.128)
#define WARRB  (2 * 8 * WQSTR)    // 5120 per array
#define WBYTES (2 * WARRB)        // 10240 per chunk
#define BUFB   (ABYTES + WBYTES)  // 30720
#define SMEM_DYN (NBUF * BUFB)    // 122880
#define SCSTR 66

static __device__ __forceinline__ uint32_t smem_u32(const void* p) {
    uint32_t a;
    asm("{ .reg .u64 t; cvta.to.shared.u64 t, %1; cvt.u32.u64 %0, t; }"
        : "=r"(a) : "l"(p));
    return a;
}
static __device__ __forceinline__ void cp16(uint32_t dst, const void* src) {
    asm volatile("cp.async.cg.shared.global [%0], [%1], 16;"
                 :: "r"(dst), "l"(src) : "memory");
}
#define CP_COMMIT() asm volatile("cp.async.commit_group;" ::: "memory")
#define CP_WAIT(n)  asm volatile("cp.async.wait_group %0;" :: "n"(n) : "memory")

// A split: hi = rz-f16 pack (== mantissa-mask in normal range), lo = rz-f16(x - mask(x)).
static __device__ __forceinline__ void split_pair(float f0, float f1,
                                                  uint32_t& hi2, uint32_t& lo2) {
    asm("cvt.rz.f16x2.f32 %0, %1, %2;" : "=r"(hi2) : "f"(f1), "f"(f0));
    const float m0 = __uint_as_float(__float_as_uint(f0) & 0xffffe000u);
    const float m1 = __uint_as_float(__float_as_uint(f1) & 0xffffe000u);
    const float r0 = f0 - m0, r1 = f1 - m1;
    asm("cvt.rz.f16x2.f32 %0, %1, %2;" : "=r"(lo2) : "f"(r1), "f"(r0));
}
static __device__ __forceinline__ void mma16(float* c, const uint32_t* a,
                                             uint32_t b0, uint32_t b1) {
    asm volatile(
        "mma.sync.aligned.m16n8k16.row.col.f32.f16.f16.f32 "
        "{%0,%1,%2,%3}, {%4,%5,%6,%7}, {%8,%9}, {%0,%1,%2,%3};"
        : "+f"(c[0]), "+f"(c[1]), "+f"(c[2]), "+f"(c[3])
        : "r"(a[0]), "r"(a[1]), "r"(a[2]), "r"(a[3]), "r"(b0), "r"(b1));
}

// Packed, pre-split W: per chunk [hi|lo][nhalf][qid][kpair*16B (+64B pad)].
// Entry (chunk, arr, nhalf, qid, kpair, nt) holds f16x2 of
// W[n = nhalf*32 + nt*8 + qid][k = chunk*32 + kpair*2 .. +1].
__device__ __align__(16) char g_wpack[NCH * WBYTES];

__global__ void pack_w_kernel(const float* __restrict__ W) {
    const int i = blockIdx.x * blockDim.x + threadIdx.x;   // 64*128*16 = 131072
    if (i >= NE * NCH * 16) return;
    const int kpair = i & 15;
    const int chunk = (i >> 4) & (NCH - 1);
    const int e     = i >> 11;
    const int nhalf = e >> 5, rem = e & 31, nt = rem >> 3, qid = rem & 7;
    const int k0 = chunk * KT + kpair * 2;
    const float w0 = W[(size_t)e * DIM + k0];
    const float w1 = W[(size_t)e * DIM + k0 + 1];
    const __half h0 = __float2half_rn(w0), h1 = __float2half_rn(w1);
    const __half l0 = __float2half_rn(w0 - __half2float(h0));
    const __half l1 = __float2half_rn(w1 - __half2float(h1));
    const uint32_t hi = ((uint32_t)__half_as_ushort(h1) << 16) | __half_as_ushort(h0);
    const uint32_t lo = ((uint32_t)__half_as_ushort(l1) << 16) | __half_as_ushort(l0);
    const uint32_t base = (uint32_t)chunk * WBYTES
                        + (uint32_t)(nhalf * 8 + qid) * WQSTR + kpair * 16 + nt * 4;
    *(uint32_t*)(g_wpack + base)         = hi;
    *(uint32_t*)(g_wpack + base + WARRB) = lo;
}

__global__ __launch_bounds__(NTHR, 1)
void gating_mma(const float* __restrict__ X, const float* __restrict__ B,
                float* __restrict__ out, int voff)
{
    extern __shared__ char smem[];
    const int tid    = threadIdx.x;
    const int wid    = tid >> 5;
    const int lane   = tid & 31;
    const int qid    = lane >> 2;
    const int qt     = lane & 3;
    const int stripe = wid & 3;          // m32 stripe 0..3
    const int nhalf  = (wid >> 2) & 1;   // experts [nhalf*32, +32)
    const int khalf  = wid >> 3;         // k16 half within each chunk
    const int token0 = blockIdx.x * BT;

    const uint32_t sbase = smem_u32(smem);

    // ---- producers ----
    // A: 128 rows x 8 segs(16B) = 1024 cp16 -> 2 per thread
    const int ar = tid >> 3, as = tid & 7;
    const float* agp0 = X + (size_t)(token0 + ar) * DIM + as * 4;
    const float* agp1 = agp0 + (size_t)64 * DIM;
    const uint32_t aoff0 = (uint32_t)ar * (ASTR * 4) + as * 16;
    const uint32_t aoff1 = aoff0 + 64 * (ASTR * 4);
    // W: 10240 B = 640 cp16 -> 1 per thread + 1 for tid<128, linear copy
    const char* wsrc0 = g_wpack + tid * 16;
    const char* wsrc1 = g_wpack + 8192 + tid * 16;
    const uint32_t woff0 = ABYTES + tid * 16;
    const uint32_t woff1 = ABYTES + 8192 + tid * 16;

    auto issue_chunk = [&](int c) {
        const uint32_t bb = sbase + (uint32_t)(c & (NBUF - 1)) * BUFB;
        cp16(bb + aoff0, agp0 + c * KT);
        cp16(bb + aoff1, agp1 + c * KT);
        cp16(bb + woff0, wsrc0 + (size_t)c * WBYTES);
        if (tid < 128) cp16(bb + woff1, wsrc1 + (size_t)c * WBYTES);
    };

    float acc[2][4][4];
    #pragma unroll
    for (int mi = 0; mi < 2; mi++)
        #pragma unroll
        for (int nt = 0; nt < 4; nt++)
            #pragma unroll
            for (int j = 0; j < 4; j++) acc[mi][nt][j] = 0.f;

    issue_chunk(0); CP_COMMIT();
    issue_chunk(1); CP_COMMIT();
    issue_chunk(2); CP_COMMIT();

    const int ar0   = (stripe * 32 + qid) * ASTR + khalf * 16;
    const uint32_t wlane = (uint32_t)(nhalf * 8 + qid) * WQSTR + (khalf * 8 + qt) * 16;

    #pragma unroll 1
    for (int c = 0; c < NCH; c++) {
        CP_WAIT(2);
        __syncthreads();

        const char* buf = smem + (c & (NBUF - 1)) * BUFB;
        const float* As = (const float*)buf;
        const char* Wp  = buf + ABYTES;

        // A fragments for two m16 sub-tiles
        uint32_t ah[2][4], al[2][4];
        #pragma unroll
        for (int mi = 0; mi < 2; mi++) {
            const int r = ar0 + mi * 16 * ASTR;
            const float2 a00 = *(const float2*)&As[r + 2 * qt];
            const float2 a10 = *(const float2*)&As[r + 8 * ASTR + 2 * qt];
            const float2 a01 = *(const float2*)&As[r + 2 * qt + 8];
            const float2 a11 = *(const float2*)&As[r + 8 * ASTR + 2 * qt + 8];
            split_pair(a00.x, a00.y, ah[mi][0], al[mi][0]);
            split_pair(a10.x, a10.y, ah[mi][1], al[mi][1]);
            split_pair(a01.x, a01.y, ah[mi][2], al[mi][2]);
            split_pair(a11.x, a11.y, ah[mi][3], al[mi][3]);
        }

        // B fragments: 4x LDS.128 (hi b0, hi b1, lo b0, lo b1; word nt = n-tile nt)
        const uint4 vh0 = *(const uint4*)(Wp + wlane);
        const uint4 vh1 = *(const uint4*)(Wp + wlane + 64);
        const uint4 vl0 = *(const uint4*)(Wp + wlane + WARRB);
        const uint4 vl1 = *(const uint4*)(Wp + wlane + WARRB + 64);
        const uint32_t bh0[4] = {vh0.x, vh0.y, vh0.z, vh0.w};
        const uint32_t bh1[4] = {vh1.x, vh1.y, vh1.z, vh1.w};
        const uint32_t bl0[4] = {vl0.x, vl0.y, vl0.z, vl0.w};
        const uint32_t bl1[4] = {vl1.x, vl1.y, vl1.z, vl1.w};

        #pragma unroll
        for (int mi = 0; mi < 2; mi++)
            #pragma unroll
            for (int nt = 0; nt < 4; nt++) mma16(acc[mi][nt], ah[mi], bh0[nt], bh1[nt]);
        #pragma unroll
        for (int mi = 0; mi < 2; mi++)
            #pragma unroll
            for (int nt = 0; nt < 4; nt++) mma16(acc[mi][nt], ah[mi], bl0[nt], bl1[nt]);
        #pragma unroll
        for (int mi = 0; mi < 2; mi++)
            #pragma unroll
            for (int nt = 0; nt < 4; nt++) mma16(acc[mi][nt], al[mi], bh0[nt], bh1[nt]);

        if (c + 3 < NCH) issue_chunk(c + 3);
        CP_COMMIT();   // uniform group accounting
    }

    CP_WAIT(0);
    __syncthreads();

    // ---- scores -> two smem banks (khalf partials), bias fused into bank 0 ----
    float* SC = (float*)smem;
    {
        float* SCk = SC + khalf * (BT * SCSTR);
        #pragma unroll
        for (int mi = 0; mi < 2; mi++) {
            const int r0 = stripe * 32 + mi * 16 + qid, r1 = r0 + 8;
            #pragma unroll
            for (int nt = 0; nt < 4; nt++) {
                const int cb = nhalf * 32 + nt * 8 + qt * 2;
                const float b0 = khalf ? 0.f : __ldg(B + cb);
                const float b1 = khalf ? 0.f : __ldg(B + cb + 1);
                *(float2*)(SCk + r0 * SCSTR + cb) =
                    make_float2(acc[mi][nt][0] + b0, acc[mi][nt][1] + b1);
                *(float2*)(SCk + r1 * SCSTR + cb) =
                    make_float2(acc[mi][nt][2] + b0, acc[mi][nt][3] + b1);
            }
        }
    }
    __syncthreads();

    if (tid < BT) {
        const float* row0 = SC + tid * SCSTR;
        const float* row1 = row0 + BT * SCSTR;

        float sc[NE];
        #pragma unroll
        for (int e = 0; e < NE; e++) sc[e] = row0[e] + row1[e];

        float m = sc[0];
        #pragma unroll
        for (int e = 1; e < NE; e++) m = fmaxf(m, sc[e]);

        float se = 0.f;
        #pragma unroll
        for (int e = 0; e < NE; e++) se += __expf(sc[e] - m);

        float v1 = -1e30f, v2 = -1e30f; int i1 = -1, i2 = -1;
        #pragma unroll
        for (int e = 0; e < NE; e++) {
            const float s = sc[e];
            if (s > v1)      { v2 = v1; i2 = i1; v1 = s; i1 = e; }
            else if (s > v2) { v2 = s; i2 = e; }
        }

        const int g = token0 + tid;
        const float inv = 1.0f / se;
        out[g * 2 + 0]        = (float)i1;
        out[g * 2 + 1]        = (float)i2;
        out[voff + g * 2 + 0] = __expf(v1 - m) * inv;
        out[voff + g * 2 + 1] = __expf(v2 - m) * inv;
    }
}

extern "C" void kernel_launch(void* const* d_in, const int* in_sizes, int n_in,
                              void* d_out, int out_size) {
    const float* x = (const float*)d_in[0];
    const float* W = (const float*)d_in[1];
    const float* b = (const float*)d_in[2];
    float* out = (float*)d_out;

    pack_w_kernel<<<(NE * NCH * 16 + 255) / 256, 256>>>(W);

    cudaFuncSetAttribute(gating_mma, cudaFuncAttributeMaxDynamicSharedMemorySize, SMEM_DYN);
    gating_mma<<<NTOK / BT, NTHR, SMEM_DYN>>>(x, b, out, out_size / 2);
}

// round 13
// speedup vs baseline: 3.1845x; 1.0311x over previous
#include <cuda_runtime.h>
#include <cuda_fp16.h>
#include <cstdint>
#include <math.h>

#define NTOK 16384
#define DIM  4096
#define NE   64
#define BT   64                   // tokens per CTA (M): 4 m16 stripes
#define KT   32                   // K per chunk (2 k16 halves, split across warps)
#define NCH  (DIM / KT)           // 128
#define NBUF 4
#define NTHR 512
#define ASTR 40                   // A smem stride in floats (LDS.64 bank-clean)
#define ABYTES (BT * ASTR * 4)    // 10240
// packed W tile: [arr 2][nhalf 2][qid 8][kpair 16 x 4B x 4nt + 64B pad]
#define WQSTR  320
#define WARRB  (2 * 8 * WQSTR)    // 5120 per array
#define WBYTES (2 * WARRB)        // 10240 per chunk
#define BUFB   (ABYTES + WBYTES)  // 20480
#define SMEM_DYN (NBUF * BUFB)    // 81920  (x2 CTAs = 160KB/SM)
#define SCSTR 66

static __device__ __forceinline__ uint32_t smem_u32(const void* p) {
    uint32_t a;
    asm("{ .reg .u64 t; cvta.to.shared.u64 t, %1; cvt.u32.u64 %0, t; }"
        : "=r"(a) : "l"(p));
    return a;
}
static __device__ __forceinline__ void cp16(uint32_t dst, const void* src) {
    asm volatile("cp.async.cg.shared.global [%0], [%1], 16;"
                 :: "r"(dst), "l"(src) : "memory");
}
#define CP_COMMIT() asm volatile("cp.async.commit_group;" ::: "memory")
#define CP_WAIT(n)  asm volatile("cp.async.wait_group %0;" :: "n"(n) : "memory")

// A split: hi = rz-f16 pack (== mantissa-mask in normal range), lo = rz-f16(x - mask(x)).
static __device__ __forceinline__ void split_pair(float f0, float f1,
                                                  uint32_t& hi2, uint32_t& lo2) {
    asm("cvt.rz.f16x2.f32 %0, %1, %2;" : "=r"(hi2) : "f"(f1), "f"(f0));
    const float m0 = __uint_as_float(__float_as_uint(f0) & 0xffffe000u);
    const float m1 = __uint_as_float(__float_as_uint(f1) & 0xffffe000u);
    const float r0 = f0 - m0, r1 = f1 - m1;
    asm("cvt.rz.f16x2.f32 %0, %1, %2;" : "=r"(lo2) : "f"(r1), "f"(r0));
}
static __device__ __forceinline__ void mma16(float* c, const uint32_t* a,
                                             uint32_t b0, uint32_t b1) {
    asm volatile(
        "mma.sync.aligned.m16n8k16.row.col.f32.f16.f16.f32 "
        "{%0,%1,%2,%3}, {%4,%5,%6,%7}, {%8,%9}, {%0,%1,%2,%3};"
        : "+f"(c[0]), "+f"(c[1]), "+f"(c[2]), "+f"(c[3])
        : "r"(a[0]), "r"(a[1]), "r"(a[2]), "r"(a[3]), "r"(b0), "r"(b1));
}

// Packed, pre-split W (same layout as R12): per chunk [hi|lo][nhalf][qid][kpair].
__device__ __align__(16) char g_wpack[NCH * WBYTES];

__global__ void pack_w_kernel(const float* __restrict__ W) {
    const int i = blockIdx.x * blockDim.x + threadIdx.x;   // 131072
    if (i >= NE * NCH * 16) return;
    const int kpair = i & 15;
    const int chunk = (i >> 4) & (NCH - 1);
    const int e     = i >> 11;
    const int nhalf = e >> 5, rem = e & 31, nt = rem >> 3, qid = rem & 7;
    const int k0 = chunk * KT + kpair * 2;
    const float w0 = W[(size_t)e * DIM + k0];
    const float w1 = W[(size_t)e * DIM + k0 + 1];
    const __half h0 = __float2half_rn(w0), h1 = __float2half_rn(w1);
    const __half l0 = __float2half_rn(w0 - __half2float(h0));
    const __half l1 = __float2half_rn(w1 - __half2float(h1));
    const uint32_t hi = ((uint32_t)__half_as_ushort(h1) << 16) | __half_as_ushort(h0);
    const uint32_t lo = ((uint32_t)__half_as_ushort(l1) << 16) | __half_as_ushort(l0);
    const uint32_t base = (uint32_t)chunk * WBYTES
                        + (uint32_t)(nhalf * 8 + qid) * WQSTR + kpair * 16 + nt * 4;
    *(uint32_t*)(g_wpack + base)         = hi;
    *(uint32_t*)(g_wpack + base + WARRB) = lo;
}

__global__ __launch_bounds__(NTHR, 2)
void gating_mma(const float* __restrict__ X, const float* __restrict__ B,
                float* __restrict__ out, int voff)
{
    extern __shared__ char smem[];
    const int tid    = threadIdx.x;
    const int wid    = tid >> 5;
    const int lane   = tid & 31;
    const int qid    = lane >> 2;
    const int qt     = lane & 3;
    const int stripe = wid & 3;          // m16 stripe 0..3
    const int nhalf  = (wid >> 2) & 1;   // experts [nhalf*32, +32)
    const int khalf  = wid >> 3;         // k16 half within each chunk
    const int token0 = blockIdx.x * BT;

    const uint32_t sbase = smem_u32(smem);

    // ---- producers ----
    // A: 64 rows x 8 segs(16B) = 512 cp16 -> 1 per thread
    const int ar = tid >> 3, as = tid & 7;
    const float* agp = X + (size_t)(token0 + ar) * DIM + as * 4;
    const uint32_t aoff = (uint32_t)ar * (ASTR * 4) + as * 16;
    // W: 10240 B = 640 cp16 -> 1 per thread + 1 for tid<128
    const char* wsrc0 = g_wpack + tid * 16;
    const char* wsrc1 = g_wpack + 8192 + tid * 16;
    const uint32_t woff0 = ABYTES + tid * 16;
    const uint32_t woff1 = ABYTES + 8192 + tid * 16;

    auto issue_chunk = [&](int c) {
        const uint32_t bb = sbase + (uint32_t)(c & (NBUF - 1)) * BUFB;
        cp16(bb + aoff, agp + c * KT);
        cp16(bb + woff0, wsrc0 + (size_t)c * WBYTES);
        if (tid < 128) cp16(bb + woff1, wsrc1 + (size_t)c * WBYTES);
    };

    float acc[4][4];
    #pragma unroll
    for (int nt = 0; nt < 4; nt++)
        #pragma unroll
        for (int j = 0; j < 4; j++) acc[nt][j] = 0.f;

    issue_chunk(0); CP_COMMIT();
    issue_chunk(1); CP_COMMIT();
    issue_chunk(2); CP_COMMIT();

    const int ar0 = (stripe * 16 + qid) * ASTR + khalf * 16;
    const uint32_t wlane = (uint32_t)(nhalf * 8 + qid) * WQSTR + (khalf * 8 + qt) * 16;

    #pragma unroll 1
    for (int c = 0; c < NCH; c++) {
        CP_WAIT(2);
        __syncthreads();

        const char* buf = smem + (c & (NBUF - 1)) * BUFB;
        const float* As = (const float*)buf;
        const char* Wp  = buf + ABYTES;

        // A fragment
        const float2 a00 = *(const float2*)&As[ar0 + 2 * qt];
        const float2 a10 = *(const float2*)&As[ar0 + 8 * ASTR + 2 * qt];
        const float2 a01 = *(const float2*)&As[ar0 + 2 * qt + 8];
        const float2 a11 = *(const float2*)&As[ar0 + 8 * ASTR + 2 * qt + 8];
        uint32_t ah[4], al[4];
        split_pair(a00.x, a00.y, ah[0], al[0]);
        split_pair(a10.x, a10.y, ah[1], al[1]);
        split_pair(a01.x, a01.y, ah[2], al[2]);
        split_pair(a11.x, a11.y, ah[3], al[3]);

        // B fragments: 4x LDS.128
        const uint4 vh0 = *(const uint4*)(Wp + wlane);
        const uint4 vh1 = *(const uint4*)(Wp + wlane + 64);
        const uint4 vl0 = *(const uint4*)(Wp + wlane + WARRB);
        const uint4 vl1 = *(const uint4*)(Wp + wlane + WARRB + 64);
        const uint32_t bh0[4] = {vh0.x, vh0.y, vh0.z, vh0.w};
        const uint32_t bh1[4] = {vh1.x, vh1.y, vh1.z, vh1.w};
        const uint32_t bl0[4] = {vl0.x, vl0.y, vl0.z, vl0.w};
        const uint32_t bl1[4] = {vl1.x, vl1.y, vl1.z, vl1.w};

        #pragma unroll
        for (int nt = 0; nt < 4; nt++) mma16(acc[nt], ah, bh0[nt], bh1[nt]); // Ah*Bh
        #pragma unroll
        for (int nt = 0; nt < 4; nt++) mma16(acc[nt], ah, bl0[nt], bl1[nt]); // Ah*Bl
        #pragma unroll
        for (int nt = 0; nt < 4; nt++) mma16(acc[nt], al, bh0[nt], bh1[nt]); // Al*Bh

        if (c + 3 < NCH) issue_chunk(c + 3);
        CP_COMMIT();   // uniform group accounting
    }

    CP_WAIT(0);
    __syncthreads();

    // ---- scores -> two smem banks (khalf partials), bias fused into bank 0 ----
    float* SC = (float*)smem;
    {
        float* SCk = SC + khalf * (BT * SCSTR);
        const int r0 = stripe * 16 + qid, r1 = r0 + 8;
        #pragma unroll
        for (int nt = 0; nt < 4; nt++) {
            const int cb = nhalf * 32 + nt * 8 + qt * 2;
            const float b0 = khalf ? 0.f : __ldg(B + cb);
            const float b1 = khalf ? 0.f : __ldg(B + cb + 1);
            *(float2*)(SCk + r0 * SCSTR + cb) = make_float2(acc[nt][0] + b0, acc[nt][1] + b1);
            *(float2*)(SCk + r1 * SCSTR + cb) = make_float2(acc[nt][2] + b0, acc[nt][3] + b1);
        }
    }
    __syncthreads();

    if (tid < BT) {
        const float* row0 = SC + tid * SCSTR;
        const float* row1 = row0 + BT * SCSTR;

        float sc[NE];
        #pragma unroll
        for (int e = 0; e < NE; e++) sc[e] = row0[e] + row1[e];

        float m = sc[0];
        #pragma unroll
        for (int e = 1; e < NE; e++) m = fmaxf(m, sc[e]);

        float se = 0.f;
        #pragma unroll
        for (int e = 0; e < NE; e++) se += __expf(sc[e] - m);

        float v1 = -1e30f, v2 = -1e30f; int i1 = -1, i2 = -1;
        #pragma unroll
        for (int e = 0; e < NE; e++) {
            const float s = sc[e];
            if (s > v1)      { v2 = v1; i2 = i1; v1 = s; i1 = e; }
            else if (s > v2) { v2 = s; i2 = e; }
        }

        const int g = token0 + tid;
        const float inv = 1.0f / se;
        out[g * 2 + 0]        = (float)i1;
        out[g * 2 + 1]        = (float)i2;
        out[voff + g * 2 + 0] = __expf(v1 - m) * inv;
        out[voff + g * 2 + 1] = __expf(v2 - m) * inv;
    }
}

extern "C" void kernel_launch(void* const* d_in, const int* in_sizes, int n_in,
                              void* d_out, int out_size) {
    const float* x = (const float*)d_in[0];
    const float* W = (const float*)d_in[1];
    const float* b = (const float*)d_in[2];
    float* out = (float*)d_out;

    pack_w_kernel<<<(NE * NCH * 16 + 255) / 256, 256>>>(W);

    cudaFuncSetAttribute(gating_mma, cudaFuncAttributeMaxDynamicSharedMemorySize, SMEM_DYN);
    gating_mma<<<NTOK / BT, NTHR, SMEM_DYN>>>(x, b, out, out_size / 2);
}